// round 12
// baseline (speedup 1.0000x reference)
#include <cuda_runtime.h>
#include <cuda_bf16.h>
#include <cstdint>

// Problem constants
#define BB 4
#define LL 1024
#define DD 1024
#define HH 16
#define HD 64
#define MROWS 4096           // B*L
#define PEN 2049

// Scratch (device globals; allocation is forbidden)
__device__ __nv_bfloat16 g_xh[MROWS * DD];
__device__ __nv_bfloat16 g_xl[MROWS * DD];
__device__ __nv_bfloat16 g_wqh[DD * DD];
__device__ __nv_bfloat16 g_wql[DD * DD];
__device__ __nv_bfloat16 g_wkh[DD * DD];
__device__ __nv_bfloat16 g_wkl[DD * DD];
__device__ __nv_bfloat16 g_wvh[DD * DD];
__device__ __nv_bfloat16 g_wvl[DD * DD];
__device__ __nv_bfloat16 g_wh[DD * DD];
__device__ __nv_bfloat16 g_wl[DD * DD];
__device__ __nv_bfloat16 g_Qh[MROWS * DD];
__device__ __nv_bfloat16 g_Ql[MROWS * DD];
__device__ __nv_bfloat16 g_Kh[MROWS * DD];
__device__ __nv_bfloat16 g_Kl[MROWS * DD];
__device__ __nv_bfloat16 g_Vh[MROWS * DD];
__device__ __nv_bfloat16 g_Vl[MROWS * DD];
__device__ __nv_bfloat16 g_Oh[MROWS * DD];
__device__ __nv_bfloat16 g_Ol[MROWS * DD];
__device__ __nv_bfloat16 g_pekh[PEN * HD];
__device__ __nv_bfloat16 g_pekl[PEN * HD];
__device__ __nv_bfloat16 g_pevh[PEN * HD];
__device__ __nv_bfloat16 g_pevl[PEN * HD];

__device__ __forceinline__ uint32_t smem_u32(const void* p) {
    uint32_t a;
    asm("{ .reg .u64 t; cvta.to.shared.u64 t, %1; cvt.u32.u64 %0, t; }" : "=r"(a) : "l"(p));
    return a;
}

#define MMA_OP(c, af, bf) \
    asm volatile("mma.sync.aligned.m16n8k16.row.col.f32.bf16.bf16.f32 " \
                 "{%0,%1,%2,%3}, {%4,%5,%6,%7}, {%8,%9}, {%0,%1,%2,%3};" \
                 : "+f"((c)[0]), "+f"((c)[1]), "+f"((c)[2]), "+f"((c)[3]) \
                 : "r"((af)[0]), "r"((af)[1]), "r"((af)[2]), "r"((af)[3]), \
                   "r"((bf)[0]), "r"((bf)[1]))

#define LDSM4(d0,d1,d2,d3,a) \
    asm volatile("ldmatrix.sync.aligned.m8n8.x4.shared.b16 {%0,%1,%2,%3}, [%4];" \
                 : "=r"(d0), "=r"(d1), "=r"(d2), "=r"(d3) : "r"(a))
#define LDSM4T(d0,d1,d2,d3,a) \
    asm volatile("ldmatrix.sync.aligned.m8n8.x4.trans.shared.b16 {%0,%1,%2,%3}, [%4];" \
                 : "=r"(d0), "=r"(d1), "=r"(d2), "=r"(d3) : "r"(a))

#define CP16(dst, src) \
    asm volatile("cp.async.cg.shared.global [%0], [%1], 16;" :: "r"(dst), "l"(src))
#define CPWAIT() \
    asm volatile("cp.async.commit_group;\n\tcp.async.wait_group 0;" ::: "memory")

__device__ __forceinline__ uint32_t pack2(__nv_bfloat16 a, __nv_bfloat16 b) {
    __nv_bfloat162 t(a, b);
    return *reinterpret_cast<uint32_t*>(&t);
}
__device__ __forceinline__ uint16_t bf16bits(__nv_bfloat16 h) {
    return *reinterpret_cast<uint16_t*>(&h);
}

// ---------------------------------------------------------------------------
// fp32 -> bf16 hi/lo split
// ---------------------------------------------------------------------------
__device__ __forceinline__ void split4(const float* s, __nv_bfloat16* h,
                                       __nv_bfloat16* l, int i) {
    float4 v = ((const float4*)s)[i];
    __nv_bfloat16 h0 = __float2bfloat16(v.x);
    __nv_bfloat16 h1 = __float2bfloat16(v.y);
    __nv_bfloat16 h2 = __float2bfloat16(v.z);
    __nv_bfloat16 h3 = __float2bfloat16(v.w);
    __nv_bfloat16 l0 = __float2bfloat16(v.x - __bfloat162float(h0));
    __nv_bfloat16 l1 = __float2bfloat16(v.y - __bfloat162float(h1));
    __nv_bfloat16 l2 = __float2bfloat16(v.z - __bfloat162float(h2));
    __nv_bfloat16 l3 = __float2bfloat16(v.w - __bfloat162float(h3));
    ((uint2*)h)[i] = make_uint2(pack2(h0, h1), pack2(h2, h3));
    ((uint2*)l)[i] = make_uint2(pack2(l0, l1), pack2(l2, l3));
}

__global__ __launch_bounds__(256)
void split_kernel(const float* __restrict__ s, __nv_bfloat16* __restrict__ h,
                  __nv_bfloat16* __restrict__ l, int n4) {
    int i = blockIdx.x * 256 + threadIdx.x;
    if (i >= n4) return;
    split4(s, h, l, i);
}

__global__ __launch_bounds__(256)
void split6_kernel(const float* __restrict__ x, const float* __restrict__ Wq,
                   const float* __restrict__ Wk, const float* __restrict__ Wv,
                   const float* __restrict__ pek, const float* __restrict__ pev,
                   __nv_bfloat16* __restrict__ xh, __nv_bfloat16* __restrict__ xl,
                   __nv_bfloat16* __restrict__ wqh, __nv_bfloat16* __restrict__ wql,
                   __nv_bfloat16* __restrict__ wkh, __nv_bfloat16* __restrict__ wkl,
                   __nv_bfloat16* __restrict__ wvh, __nv_bfloat16* __restrict__ wvl,
                   __nv_bfloat16* __restrict__ pkh, __nv_bfloat16* __restrict__ pkl,
                   __nv_bfloat16* __restrict__ pvh, __nv_bfloat16* __restrict__ pvl) {
    int blk = blockIdx.x;
    const float* s; __nv_bfloat16 *h, *l; int i, n4;
    if (blk < 4096)      { s = x;   h = xh;  l = xl;  i = blk * 256 + threadIdx.x; n4 = 1048576; }
    else if (blk < 5120) { s = Wq;  h = wqh; l = wql; i = (blk - 4096) * 256 + threadIdx.x; n4 = 262144; }
    else if (blk < 6144) { s = Wk;  h = wkh; l = wkl; i = (blk - 5120) * 256 + threadIdx.x; n4 = 262144; }
    else if (blk < 7168) { s = Wv;  h = wvh; l = wvl; i = (blk - 6144) * 256 + threadIdx.x; n4 = 262144; }
    else if (blk < 7297) { s = pek; h = pkh; l = pkl; i = (blk - 7168) * 256 + threadIdx.x; n4 = 32784; }
    else                 { s = pev; h = pvh; l = pvl; i = (blk - 7297) * 256 + threadIdx.x; n4 = 32784; }
    if (i >= n4) return;
    split4(s, h, l, i);
}

// ---------------------------------------------------------------------------
// mma.sync bf16x3 GEMM, 512 threads / 16 warps (4 warps per SMSP).
// Warp grid 4(m) x 4(n), warp tile 32x32. C = Ah*Bh + Ah*Bl + Al*Bh.
// ---------------------------------------------------------------------------
#define GKDIM 1024
#define NIT 32
#define TILE_B 10240
#define STAGE_B (4 * TILE_B)
#define GEMM_SMEM (2 * STAGE_B)

__global__ __launch_bounds__(512, 1)
void gemm_mma(const __nv_bfloat16* __restrict__ Ah, const __nv_bfloat16* __restrict__ Al,
              const __nv_bfloat16* __restrict__ Bh, const __nv_bfloat16* __restrict__ Bl,
              float* __restrict__ C,
              __nv_bfloat16* __restrict__ Ch, __nv_bfloat16* __restrict__ Cl) {
    extern __shared__ __align__(128) char sm[];
    const uint32_t smb = smem_u32(sm);
    const int tid = threadIdx.x;
    const int wid = tid >> 5, lane = tid & 31;
    const int m0 = blockIdx.y * 128, n0 = blockIdx.x * 128;
    const int wm = wid & 3, wn = wid >> 2;     // 4 x 4 warp grid, 32x32 tiles

    const __nv_bfloat16* srcs[4] = {
        Ah + (size_t)m0 * GKDIM, Al + (size_t)m0 * GKDIM,
        Bh + (size_t)n0 * GKDIM, Bl + (size_t)n0 * GKDIM };

    auto stage_load = [&](int kc, int s) {
#pragma unroll
        for (int rep = 0; rep < 4; ++rep) {
            int idx = tid + rep * 512;
            int tile = idx >> 9;
            int r = (idx >> 2) & 127;
            int c = idx & 3;
            const void* gp = srcs[tile] + (size_t)r * GKDIM + kc * 32 + c * 8;
            uint32_t dp = smb + s * STAGE_B + tile * TILE_B + r * 80 + c * 16;
            CP16(dp, gp);
        }
        asm volatile("cp.async.commit_group;");
    };

    float acc[2][4][4];
#pragma unroll
    for (int i = 0; i < 2; ++i)
#pragma unroll
        for (int j = 0; j < 4; ++j)
#pragma unroll
            for (int k = 0; k < 4; ++k) acc[i][j][k] = 0.f;

    stage_load(0, 0);

    for (int it = 0; it < NIT; ++it) {
        if (it + 1 < NIT) {
            stage_load(it + 1, (it + 1) & 1);
            asm volatile("cp.async.wait_group 1;");
        } else {
            asm volatile("cp.async.wait_group 0;");
        }
        __syncthreads();

        const uint32_t base = smb + (it & 1) * STAGE_B;
        const uint32_t aHb = base, aLb = base + TILE_B;
        const uint32_t bHb = base + 2 * TILE_B, bLb = base + 3 * TILE_B;
        const int arow = wm * 32 + (lane & 15);
        const int acolb = (lane & 16) >> 1;
        const int brow = wn * 32 + (lane & 7);
        const int bcolb = lane & 8;

#pragma unroll
        for (int k16 = 0; k16 < 32; k16 += 16) {
            uint32_t ah[2][4], al[2][4], bh[4][2], bl[4][2];
#pragma unroll
            for (int mi = 0; mi < 2; ++mi) {
                uint32_t ad = aHb + ((arow + mi * 16) * 40 + k16 + acolb) * 2;
                LDSM4(ah[mi][0], ah[mi][1], ah[mi][2], ah[mi][3], ad);
                uint32_t ad2 = aLb + ((arow + mi * 16) * 40 + k16 + acolb) * 2;
                LDSM4(al[mi][0], al[mi][1], al[mi][2], al[mi][3], ad2);
            }
#pragma unroll
            for (int ni = 0; ni < 4; ++ni) {
                uint32_t bd = bHb + ((brow + ni * 8) * 40 + k16 + bcolb) * 2;
                asm volatile("ldmatrix.sync.aligned.m8n8.x2.shared.b16 {%0,%1}, [%2];"
                             : "=r"(bh[ni][0]), "=r"(bh[ni][1]) : "r"(bd));
                uint32_t bd2 = bLb + ((brow + ni * 8) * 40 + k16 + bcolb) * 2;
                asm volatile("ldmatrix.sync.aligned.m8n8.x2.shared.b16 {%0,%1}, [%2];"
                             : "=r"(bl[ni][0]), "=r"(bl[ni][1]) : "r"(bd2));
            }
#pragma unroll
            for (int mi = 0; mi < 2; ++mi)
#pragma unroll
                for (int ni = 0; ni < 4; ++ni) {
                    MMA_OP(acc[mi][ni], ah[mi], bh[ni]);
                    MMA_OP(acc[mi][ni], ah[mi], bl[ni]);
                    MMA_OP(acc[mi][ni], al[mi], bh[ni]);
                }
        }
        __syncthreads();
    }

    const int crow = m0 + wm * 32 + (lane >> 2);
    const int ccol = n0 + wn * 32 + (lane & 3) * 2;
    if (Ch) {
#pragma unroll
        for (int mi = 0; mi < 2; ++mi)
#pragma unroll
            for (int ni = 0; ni < 4; ++ni) {
                size_t r0 = (size_t)(crow + mi * 16) * DD + ccol + ni * 8;
                size_t r1 = (size_t)(crow + mi * 16 + 8) * DD + ccol + ni * 8;
#pragma unroll
                for (int half = 0; half < 2; ++half) {
                    float v0 = acc[mi][ni][half * 2], v1 = acc[mi][ni][half * 2 + 1];
                    __nv_bfloat16 h0 = __float2bfloat16(v0), h1 = __float2bfloat16(v1);
                    __nv_bfloat16 q0b = __float2bfloat16(v0 - __bfloat162float(h0));
                    __nv_bfloat16 q1b = __float2bfloat16(v1 - __bfloat162float(h1));
                    size_t r = half ? r1 : r0;
                    *(uint32_t*)&Ch[r] = pack2(h0, h1);
                    *(uint32_t*)&Cl[r] = pack2(q0b, q1b);
                }
            }
    } else {
#pragma unroll
        for (int mi = 0; mi < 2; ++mi)
#pragma unroll
            for (int ni = 0; ni < 4; ++ni) {
                size_t r0 = (size_t)(crow + mi * 16) * DD + ccol + ni * 8;
                size_t r1 = (size_t)(crow + mi * 16 + 8) * DD + ccol + ni * 8;
                *(float2*)&C[r0] = make_float2(acc[mi][ni][0], acc[mi][ni][1]);
                *(float2*)&C[r1] = make_float2(acc[mi][ni][2], acc[mi][ni][3]);
            }
    }
}

// ---------------------------------------------------------------------------
// Fused flash attention, 256 threads, warp grid 4(q) x 2(n).  (unchanged R11)
// ---------------------------------------------------------------------------
#define AQH   0
#define AQL   9216
#define AKH   18432
#define AKL   27648
#define AVH   36864
#define AVL   46080
#define AEKH  55296
#define AEKL  73728
#define AEVH  92160
#define AEVL  110592
#define AU    129024
#define APH   162816
#define APL   172032
#define ASBUF 162816          // S fp32 64x68 overlays APH/APL
#define APDH  181248
#define APDL  198656
#define ASTAT 216064
#define ATTN_SMEM (216064 + 768)

__global__ __launch_bounds__(256)
void attn_fused(const __nv_bfloat16* __restrict__ Qh, const __nv_bfloat16* __restrict__ Ql,
                const __nv_bfloat16* __restrict__ Kh, const __nv_bfloat16* __restrict__ Kl,
                const __nv_bfloat16* __restrict__ Vh, const __nv_bfloat16* __restrict__ Vl,
                const __nv_bfloat16* __restrict__ Ekh, const __nv_bfloat16* __restrict__ Ekl,
                const __nv_bfloat16* __restrict__ Evh, const __nv_bfloat16* __restrict__ Evl,
                __nv_bfloat16* __restrict__ Oh, __nv_bfloat16* __restrict__ Ol) {
    extern __shared__ __align__(128) char sm[];
    const uint32_t smb = smem_u32(sm);
    const int qt = 15 - blockIdx.x;           // heavy tiles first
    const int q0 = qt * 64;
    const int bh = blockIdx.y;
    const int b = bh >> 4, h = bh & 15;
    const int tid = threadIdx.x;
    const int wid = tid >> 5, lane = tid & 31;
    const int wq = wid & 3, wn = wid >> 2;
    const int frow = lane & 15;
    const int fcolb = (lane >> 4) << 3;
    const int crow = wq * 16 + (lane >> 2);
    const int ccol = (lane & 3) * 2;
    const int srow = tid >> 2, spart = tid & 3;

    float* mS = (float*)(sm + ASTAT);
    float* lS = mS + 64;
    float* fS = mS + 128;
    float* Us = (float*)(sm + AU);
    float* Sb = (float*)(sm + ASBUF);

    if (tid < 64) { mS[tid] = -1e30f; lS[tid] = 0.f; }

    // stage Q (once)
    {
        const __nv_bfloat16* gq = Qh + (size_t)(b * LL + q0) * DD + h * HD;
        const __nv_bfloat16* gql = Ql + (size_t)(b * LL + q0) * DD + h * HD;
#pragma unroll
        for (int t = 0; t < 4; ++t) {
            int i = tid + t * 256;
            int tt = i >> 9;
            int r = (i >> 3) & 63;
            int c = i & 7;
            const __nv_bfloat16* sp = (tt ? gql : gq) + (size_t)r * DD + c * 8;
            CP16(smb + (tt ? AQL : AQH) + r * 144 + c * 16, sp);
        }
    }

    float acc[4][4];
#pragma unroll
    for (int i = 0; i < 4; ++i)
#pragma unroll
        for (int j = 0; j < 4; ++j) acc[i][j] = 0.f;

    for (int k0 = 0; k0 <= q0; k0 += 64) {
        const int base = k0 - q0 + 961;
        const bool first = (k0 == 0);
        __syncthreads();
        // stage K, V
        {
            const __nv_bfloat16* g0 = Kh + (size_t)(b * LL + k0) * DD + h * HD;
            const __nv_bfloat16* g1 = Kl + (size_t)(b * LL + k0) * DD + h * HD;
            const __nv_bfloat16* g2 = Vh + (size_t)(b * LL + k0) * DD + h * HD;
            const __nv_bfloat16* g3 = Vl + (size_t)(b * LL + k0) * DD + h * HD;
#pragma unroll
            for (int t = 0; t < 8; ++t) {
                int i = tid + t * 256;
                int tile = i >> 9;
                int r = (i >> 3) & 63;
                int c = i & 7;
                const __nv_bfloat16* sp =
                    ((tile == 0) ? g0 : (tile == 1) ? g1 : (tile == 2) ? g2 : g3)
                    + (size_t)r * DD + c * 8;
                uint32_t off = (tile == 0) ? AKH : (tile == 1) ? AKL : (tile == 2) ? AVH : AVL;
                CP16(smb + off + r * 144 + c * 16, sp);
            }
        }
        // stage Ek/Ev (circular)
        {
            int g0r = base + (first ? 0 : 64);
            int nt = first ? 16 : 8;
            int rsh = first ? 10 : 9;
            int rmask = first ? 127 : 63;
            for (int t = 0; t < nt; ++t) {
                int i = tid + t * 256;
                int tile = i >> rsh;
                int rr = (i >> 3) & rmask;
                int c = i & 7;
                int g = g0r + rr;
                const __nv_bfloat16* sp =
                    ((tile == 0) ? Ekh : (tile == 1) ? Ekl : (tile == 2) ? Evh : Evl)
                    + (size_t)g * HD + c * 8;
                uint32_t off = (tile == 0) ? AEKH : (tile == 1) ? AEKL
                             : (tile == 2) ? AEVH : AEVL;
                CP16(smb + off + (uint32_t)(g & 127) * 144 + c * 16, sp);
            }
        }
        CPWAIT();
        __syncthreads();

        // ---- S = Q·K^T and new U columns = Q·Ek^T ----
        {
            float aqk[4][4], au[8][4];
#pragma unroll
            for (int i = 0; i < 4; ++i)
#pragma unroll
                for (int j = 0; j < 4; ++j) aqk[i][j] = 0.f;
#pragma unroll
            for (int i = 0; i < 8; ++i)
#pragma unroll
                for (int j = 0; j < 4; ++j) au[i][j] = 0.f;

#pragma unroll
            for (int d16 = 0; d16 < 64; d16 += 16) {
                uint32_t ah[4], al[4];
                LDSM4(ah[0], ah[1], ah[2], ah[3],
                      smb + AQH + (wq * 16 + frow) * 144 + (d16 + fcolb) * 2);
                LDSM4(al[0], al[1], al[2], al[3],
                      smb + AQL + (wq * 16 + frow) * 144 + (d16 + fcolb) * 2);
#pragma unroll
                for (int ngl = 0; ngl < 2; ++ngl) {
                    int ng = wn * 2 + ngl;
                    uint32_t kh4[4], kl4[4];
                    LDSM4(kh4[0], kh4[1], kh4[2], kh4[3],
                          smb + AKH + (ng * 16 + frow) * 144 + (d16 + fcolb) * 2);
                    LDSM4(kl4[0], kl4[1], kl4[2], kl4[3],
                          smb + AKL + (ng * 16 + frow) * 144 + (d16 + fcolb) * 2);
                    uint32_t f0h[2] = {kh4[0], kh4[2]}, f1h[2] = {kh4[1], kh4[3]};
                    uint32_t f0l[2] = {kl4[0], kl4[2]}, f1l[2] = {kl4[1], kl4[3]};
                    MMA_OP(aqk[2 * ngl],     ah, f0h);
                    MMA_OP(aqk[2 * ngl],     ah, f0l);
                    MMA_OP(aqk[2 * ngl],     al, f0h);
                    MMA_OP(aqk[2 * ngl + 1], ah, f1h);
                    MMA_OP(aqk[2 * ngl + 1], ah, f1l);
                    MMA_OP(aqk[2 * ngl + 1], al, f1h);
                }
                if (first) {
#pragma unroll
                    for (int ngl = 0; ngl < 4; ++ngl) {
                        int lr = (wn * 4 + ngl) * 16;
                        uint32_t e4h[4], e4l[4];
                        uint32_t ra = (uint32_t)((base + lr + frow) & 127) * 144 + (d16 + fcolb) * 2;
                        LDSM4(e4h[0], e4h[1], e4h[2], e4h[3], smb + AEKH + ra);
                        LDSM4(e4l[0], e4l[1], e4l[2], e4l[3], smb + AEKL + ra);
                        uint32_t f0h[2] = {e4h[0], e4h[2]}, f1h[2] = {e4h[1], e4h[3]};
                        uint32_t f0l[2] = {e4l[0], e4l[2]}, f1l[2] = {e4l[1], e4l[3]};
                        MMA_OP(au[2 * ngl],     ah, f0h);
                        MMA_OP(au[2 * ngl],     ah, f0l);
                        MMA_OP(au[2 * ngl],     al, f0h);
                        MMA_OP(au[2 * ngl + 1], ah, f1h);
                        MMA_OP(au[2 * ngl + 1], ah, f1l);
                        MMA_OP(au[2 * ngl + 1], al, f1h);
                    }
                } else {
#pragma unroll
                    for (int ngl = 0; ngl < 2; ++ngl) {
                        int lr = 64 + (wn * 2 + ngl) * 16;
                        uint32_t e4h[4], e4l[4];
                        uint32_t ra = (uint32_t)((base + lr + frow) & 127) * 144 + (d16 + fcolb) * 2;
                        LDSM4(e4h[0], e4h[1], e4h[2], e4h[3], smb + AEKH + ra);
                        LDSM4(e4l[0], e4l[1], e4l[2], e4l[3], smb + AEKL + ra);
                        uint32_t f0h[2] = {e4h[0], e4h[2]}, f1h[2] = {e4h[1], e4h[3]};
                        uint32_t f0l[2] = {e4l[0], e4l[2]}, f1l[2] = {e4l[1], e4l[3]};
                        MMA_OP(au[2 * ngl],     ah, f0h);
                        MMA_OP(au[2 * ngl],     ah, f0l);
                        MMA_OP(au[2 * ngl],     al, f0h);
                        MMA_OP(au[2 * ngl + 1], ah, f1h);
                        MMA_OP(au[2 * ngl + 1], ah, f1l);
                        MMA_OP(au[2 * ngl + 1], al, f1h);
                    }
                }
            }
#pragma unroll
            for (int ia = 0; ia < 4; ++ia) {
                int kcol = (wn * 2 + (ia >> 1)) * 16 + (ia & 1) * 8 + ccol;
                Sb[crow * 68 + kcol]           = aqk[ia][0];
                Sb[crow * 68 + kcol + 1]       = aqk[ia][1];
                Sb[(crow + 8) * 68 + kcol]     = aqk[ia][2];
                Sb[(crow + 8) * 68 + kcol + 1] = aqk[ia][3];
            }
            int cnt = first ? 8 : 4;
            for (int ia = 0; ia < cnt; ++ia) {
                int lr = (first ? (wn * 4 + (ia >> 1)) * 16
                                : 64 + (wn * 2 + (ia >> 1)) * 16) + (ia & 1) * 8 + ccol;
                int p0 = (base + lr) & 127;
                int p1 = (base + lr + 1) & 127;
                Us[crow * 132 + p0]       = au[ia][0];
                Us[crow * 132 + p1]       = au[ia][1];
                Us[(crow + 8) * 132 + p0] = au[ia][2];
                Us[(crow + 8) * 132 + p1] = au[ia][3];
            }
        }
        __syncthreads();

        // ---- online softmax ----
        float p[16];
        {
            int qg = q0 + srow;
            float mx = -1e30f;
#pragma unroll
            for (int j = 0; j < 16; ++j) {
                int c = spart * 16 + j;
                int pc = (base + c - srow + 63) & 127;
                float s = (Sb[srow * 68 + c] + Us[srow * 132 + pc]) * 0.125f;
                if (k0 + c > qg) s = -1e30f;
                p[j] = s;
                mx = fmaxf(mx, s);
            }
            mx = fmaxf(mx, __shfl_xor_sync(0xffffffffu, mx, 1));
            mx = fmaxf(mx, __shfl_xor_sync(0xffffffffu, mx, 2));
            float mold = mS[srow];
            float mnew = fmaxf(mold, mx);
            float fct = __expf(mold - mnew);
            float rs = 0.f;
#pragma unroll
            for (int j = 0; j < 16; ++j) { p[j] = __expf(p[j] - mnew); rs += p[j]; }
            rs += __shfl_xor_sync(0xffffffffu, rs, 1);
            rs += __shfl_xor_sync(0xffffffffu, rs, 2);
            if (spart == 0) {
                mS[srow] = mnew;
                lS[srow] = lS[srow] * fct + rs;
                fS[srow] = fct;
            }
        }
        __syncthreads();

        // ---- stage P and sheared Pd ----
#pragma unroll
        for (int j2 = 0; j2 < 8; ++j2) {
            int c = spart * 16 + j2 * 2;
            float v0 = p[j2 * 2], v1 = p[j2 * 2 + 1];
            __nv_bfloat16 h0 = __float2bfloat16(v0), h1 = __float2bfloat16(v1);
            __nv_bfloat16 l0 = __float2bfloat16(v0 - __bfloat162float(h0));
            __nv_bfloat16 l1 = __float2bfloat16(v1 - __bfloat162float(h1));
            *(uint32_t*)(sm + APH + srow * 144 + c * 2) = pack2(h0, h1);
            *(uint32_t*)(sm + APL + srow * 144 + c * 2) = pack2(l0, l1);
            __nv_bfloat16 hs[2] = {h0, h1}, ls[2] = {l0, l1};
#pragma unroll
            for (int cc = 0; cc < 2; ++cc) {
                int r = c + cc - srow + 63;
                *(uint16_t*)(sm + APDH + srow * 272 + r * 2) = bf16bits(hs[cc]);
                *(uint16_t*)(sm + APDL + srow * 272 + r * 2) = bf16bits(ls[cc]);
                int rz = (r + 64) & 127;
                *(uint16_t*)(sm + APDH + srow * 272 + rz * 2) = 0;
                *(uint16_t*)(sm + APDL + srow * 272 + rz * 2) = 0;
            }
        }
        {
            float f0 = fS[crow], f1 = fS[crow + 8];
#pragma unroll
            for (int ni = 0; ni < 4; ++ni) {
                acc[ni][0] *= f0; acc[ni][1] *= f0;
                acc[ni][2] *= f1; acc[ni][3] *= f1;
            }
        }
        __syncthreads();

        // ---- O += P·V ----
#pragma unroll
        for (int k16 = 0; k16 < 64; k16 += 16) {
            uint32_t ph[4], pl[4];
            LDSM4(ph[0], ph[1], ph[2], ph[3],
                  smb + APH + (wq * 16 + frow) * 144 + (k16 + fcolb) * 2);
            LDSM4(pl[0], pl[1], pl[2], pl[3],
                  smb + APL + (wq * 16 + frow) * 144 + (k16 + fcolb) * 2);
#pragma unroll
            for (int ngl = 0; ngl < 2; ++ngl) {
                int ng = wn * 2 + ngl;
                uint32_t vh4[4], vl4[4];
                LDSM4T(vh4[0], vh4[1], vh4[2], vh4[3],
                       smb + AVH + (k16 + frow) * 144 + (ng * 16 + fcolb) * 2);
                LDSM4T(vl4[0], vl4[1], vl4[2], vl4[3],
                       smb + AVL + (k16 + frow) * 144 + (ng * 16 + fcolb) * 2);
                uint32_t f0h[2] = {vh4[0], vh4[1]}, f1h[2] = {vh4[2], vh4[3]};
                uint32_t f0l[2] = {vl4[0], vl4[1]}, f1l[2] = {vl4[2], vl4[3]};
                MMA_OP(acc[2 * ngl],     ph, f0h);
                MMA_OP(acc[2 * ngl],     ph, f0l);
                MMA_OP(acc[2 * ngl],     pl, f0h);
                MMA_OP(acc[2 * ngl + 1], ph, f1h);
                MMA_OP(acc[2 * ngl + 1], ph, f1l);
                MMA_OP(acc[2 * ngl + 1], pl, f1h);
            }
        }
        // ---- O += Pd·Ev (banded) ----
        {
            const int rs0 = 48 - wq * 16;
#pragma unroll
            for (int k5 = 0; k5 < 5; ++k5) {
                int r16 = rs0 + k5 * 16;
                uint32_t ph[4], pl[4];
                LDSM4(ph[0], ph[1], ph[2], ph[3],
                      smb + APDH + (wq * 16 + frow) * 272 + (r16 + fcolb) * 2);
                LDSM4(pl[0], pl[1], pl[2], pl[3],
                      smb + APDL + (wq * 16 + frow) * 272 + (r16 + fcolb) * 2);
#pragma unroll
                for (int ngl = 0; ngl < 2; ++ngl) {
                    int ng = wn * 2 + ngl;
                    uint32_t eh4[4], el4[4];
                    uint32_t ra = (uint32_t)((base + r16 + frow) & 127) * 144 + (ng * 16 + fcolb) * 2;
                    LDSM4T(eh4[0], eh4[1], eh4[2], eh4[3], smb + AEVH + ra);
                    LDSM4T(el4[0], el4[1], el4[2], el4[3], smb + AEVL + ra);
                    uint32_t f0h[2] = {eh4[0], eh4[1]}, f1h[2] = {eh4[2], eh4[3]};
                    uint32_t f0l[2] = {el4[0], el4[1]}, f1l[2] = {el4[2], el4[3]};
                    MMA_OP(acc[2 * ngl],     ph, f0h);
                    MMA_OP(acc[2 * ngl],     ph, f0l);
                    MMA_OP(acc[2 * ngl],     pl, f0h);
                    MMA_OP(acc[2 * ngl + 1], ph, f1h);
                    MMA_OP(acc[2 * ngl + 1], ph, f1l);
                    MMA_OP(acc[2 * ngl + 1], pl, f1h);
                }
            }
        }
    }

    // epilogue
    float inv0 = 1.f / lS[crow];
    float inv1 = 1.f / lS[crow + 8];
    __nv_bfloat16* Ogh = Oh + (size_t)(b * LL + q0) * DD + h * HD;
    __nv_bfloat16* Ogl = Ol + (size_t)(b * LL + q0) * DD + h * HD;
#pragma unroll
    for (int ia = 0; ia < 4; ++ia) {
        int col = wn * 32 + (ia >> 1) * 16 + (ia & 1) * 8 + ccol;
#pragma unroll
        for (int hf = 0; hf < 2; ++hf) {
            float v0 = acc[ia][hf * 2]     * (hf ? inv1 : inv0);
            float v1 = acc[ia][hf * 2 + 1] * (hf ? inv1 : inv0);
            __nv_bfloat16 h0 = __float2bfloat16(v0), h1 = __float2bfloat16(v1);
            __nv_bfloat16 l0 = __float2bfloat16(v0 - __bfloat162float(h0));
            __nv_bfloat16 l1 = __float2bfloat16(v1 - __bfloat162float(h1));
            size_t off = (size_t)(crow + hf * 8) * DD + col;
            *(uint32_t*)&Ogh[off] = pack2(h0, h1);
            *(uint32_t*)&Ogl[off] = pack2(l0, l1);
        }
    }
}

// ---------------------------------------------------------------------------
// Launch
// ---------------------------------------------------------------------------
extern "C" void kernel_launch(void* const* d_in, const int* in_sizes, int n_in,
                              void* d_out, int out_size) {
    const float* x   = (const float*)d_in[0];
    const float* Wq  = (const float*)d_in[1];
    const float* Wk  = (const float*)d_in[2];
    const float* Wv  = (const float*)d_in[3];
    const float* Wo  = (const float*)d_in[4];
    const float* pek = (const float*)d_in[5];
    const float* pev = (const float*)d_in[6];
    float* out = (float*)d_out;

    __nv_bfloat16 *xh, *xl, *wh, *wl, *wqh, *wql, *wkh, *wkl, *wvh, *wvl;
    __nv_bfloat16 *Qh, *Ql, *Kh, *Kl, *Vh, *Vl, *Oh, *Ol;
    __nv_bfloat16 *pekh, *pekl, *pevh, *pevl;
    cudaGetSymbolAddress((void**)&xh, g_xh);
    cudaGetSymbolAddress((void**)&xl, g_xl);
    cudaGetSymbolAddress((void**)&wh, g_wh);
    cudaGetSymbolAddress((void**)&wl, g_wl);
    cudaGetSymbolAddress((void**)&wqh, g_wqh);
    cudaGetSymbolAddress((void**)&wql, g_wql);
    cudaGetSymbolAddress((void**)&wkh, g_wkh);
    cudaGetSymbolAddress((void**)&wkl, g_wkl);
    cudaGetSymbolAddress((void**)&wvh, g_wvh);
    cudaGetSymbolAddress((void**)&wvl, g_wvl);
    cudaGetSymbolAddress((void**)&Qh, g_Qh);
    cudaGetSymbolAddress((void**)&Ql, g_Ql);
    cudaGetSymbolAddress((void**)&Kh, g_Kh);
    cudaGetSymbolAddress((void**)&Kl, g_Kl);
    cudaGetSymbolAddress((void**)&Vh, g_Vh);
    cudaGetSymbolAddress((void**)&Vl, g_Vl);
    cudaGetSymbolAddress((void**)&Oh, g_Oh);
    cudaGetSymbolAddress((void**)&Ol, g_Ol);
    cudaGetSymbolAddress((void**)&pekh, g_pekh);
    cudaGetSymbolAddress((void**)&pekl, g_pekl);
    cudaGetSymbolAddress((void**)&pevh, g_pevh);
    cudaGetSymbolAddress((void**)&pevl, g_pevl);

    cudaFuncSetAttribute(gemm_mma, cudaFuncAttributeMaxDynamicSharedMemorySize, GEMM_SMEM);
    cudaFuncSetAttribute(attn_fused, cudaFuncAttributeMaxDynamicSharedMemorySize, ATTN_SMEM);

    const int n4w = DD * DD / 4;
    dim3 ggemm(DD / 128, MROWS / 128);

    split6_kernel<<<7426, 256>>>(x, Wq, Wk, Wv, pek, pev,
                                 xh, xl, wqh, wql, wkh, wkl, wvh, wvl,
                                 pekh, pekl, pevh, pevl);
    gemm_mma<<<ggemm, 512, GEMM_SMEM>>>(xh, xl, wqh, wql, nullptr, Qh, Ql);
    gemm_mma<<<ggemm, 512, GEMM_SMEM>>>(xh, xl, wkh, wkl, nullptr, Kh, Kl);
    gemm_mma<<<ggemm, 512, GEMM_SMEM>>>(xh, xl, wvh, wvl, nullptr, Vh, Vl);
    split_kernel<<<(n4w + 255) / 256, 256>>>(Wo, wh, wl, n4w);
    attn_fused<<<dim3(16, 64), 256, ATTN_SMEM>>>(Qh, Ql, Kh, Kl, Vh, Vl,
                                                 pekh, pekl, pevh, pevl, Oh, Ol);
    gemm_mma<<<ggemm, 512, GEMM_SMEM>>>(Oh, Ol, wh, wl, out, nullptr, nullptr);
}

// round 13
// speedup vs baseline: 1.1015x; 1.1015x over previous
#include <cuda_runtime.h>
#include <cuda_bf16.h>
#include <cstdint>

// Problem constants
#define BB 4
#define LL 1024
#define DD 1024
#define HH 16
#define HD 64
#define MROWS 4096           // B*L
#define PEN 2049

// Scratch (device globals; allocation is forbidden)
__device__ __nv_bfloat16 g_xh[MROWS * DD];
__device__ __nv_bfloat16 g_xl[MROWS * DD];
__device__ __nv_bfloat16 g_wqh[DD * DD];
__device__ __nv_bfloat16 g_wql[DD * DD];
__device__ __nv_bfloat16 g_wkh[DD * DD];
__device__ __nv_bfloat16 g_wkl[DD * DD];
__device__ __nv_bfloat16 g_wvh[DD * DD];
__device__ __nv_bfloat16 g_wvl[DD * DD];
__device__ __nv_bfloat16 g_wh[DD * DD];
__device__ __nv_bfloat16 g_wl[DD * DD];
__device__ __nv_bfloat16 g_Qh[MROWS * DD];
__device__ __nv_bfloat16 g_Ql[MROWS * DD];
__device__ __nv_bfloat16 g_Kh[MROWS * DD];
__device__ __nv_bfloat16 g_Kl[MROWS * DD];
__device__ __nv_bfloat16 g_Vh[MROWS * DD];
__device__ __nv_bfloat16 g_Vl[MROWS * DD];
__device__ __nv_bfloat16 g_Oh[MROWS * DD];
__device__ __nv_bfloat16 g_Ol[MROWS * DD];
__device__ __nv_bfloat16 g_pekh[PEN * HD];
__device__ __nv_bfloat16 g_pekl[PEN * HD];
__device__ __nv_bfloat16 g_pevh[PEN * HD];
__device__ __nv_bfloat16 g_pevl[PEN * HD];

__device__ __forceinline__ uint32_t smem_u32(const void* p) {
    uint32_t a;
    asm("{ .reg .u64 t; cvta.to.shared.u64 t, %1; cvt.u32.u64 %0, t; }" : "=r"(a) : "l"(p));
    return a;
}

#define MMA_OP(c, af, bf) \
    asm volatile("mma.sync.aligned.m16n8k16.row.col.f32.bf16.bf16.f32 " \
                 "{%0,%1,%2,%3}, {%4,%5,%6,%7}, {%8,%9}, {%0,%1,%2,%3};" \
                 : "+f"((c)[0]), "+f"((c)[1]), "+f"((c)[2]), "+f"((c)[3]) \
                 : "r"((af)[0]), "r"((af)[1]), "r"((af)[2]), "r"((af)[3]), \
                   "r"((bf)[0]), "r"((bf)[1]))

#define LDSM4(d0,d1,d2,d3,a) \
    asm volatile("ldmatrix.sync.aligned.m8n8.x4.shared.b16 {%0,%1,%2,%3}, [%4];" \
                 : "=r"(d0), "=r"(d1), "=r"(d2), "=r"(d3) : "r"(a))
#define LDSM4T(d0,d1,d2,d3,a) \
    asm volatile("ldmatrix.sync.aligned.m8n8.x4.trans.shared.b16 {%0,%1,%2,%3}, [%4];" \
                 : "=r"(d0), "=r"(d1), "=r"(d2), "=r"(d3) : "r"(a))

#define CP16(dst, src) \
    asm volatile("cp.async.cg.shared.global [%0], [%1], 16;" :: "r"(dst), "l"(src))
#define CPWAIT() \
    asm volatile("cp.async.commit_group;\n\tcp.async.wait_group 0;" ::: "memory")

__device__ __forceinline__ uint32_t pack2(__nv_bfloat16 a, __nv_bfloat16 b) {
    __nv_bfloat162 t(a, b);
    return *reinterpret_cast<uint32_t*>(&t);
}
__device__ __forceinline__ uint16_t bf16bits(__nv_bfloat16 h) {
    return *reinterpret_cast<uint16_t*>(&h);
}

// ---------------------------------------------------------------------------
// fp32 -> bf16 hi/lo split
// ---------------------------------------------------------------------------
__device__ __forceinline__ void split4(const float* s, __nv_bfloat16* h,
                                       __nv_bfloat16* l, int i) {
    float4 v = ((const float4*)s)[i];
    __nv_bfloat16 h0 = __float2bfloat16(v.x);
    __nv_bfloat16 h1 = __float2bfloat16(v.y);
    __nv_bfloat16 h2 = __float2bfloat16(v.z);
    __nv_bfloat16 h3 = __float2bfloat16(v.w);
    __nv_bfloat16 l0 = __float2bfloat16(v.x - __bfloat162float(h0));
    __nv_bfloat16 l1 = __float2bfloat16(v.y - __bfloat162float(h1));
    __nv_bfloat16 l2 = __float2bfloat16(v.z - __bfloat162float(h2));
    __nv_bfloat16 l3 = __float2bfloat16(v.w - __bfloat162float(h3));
    ((uint2*)h)[i] = make_uint2(pack2(h0, h1), pack2(h2, h3));
    ((uint2*)l)[i] = make_uint2(pack2(l0, l1), pack2(l2, l3));
}

__global__ __launch_bounds__(256)
void split_kernel(const float* __restrict__ s, __nv_bfloat16* __restrict__ h,
                  __nv_bfloat16* __restrict__ l, int n4) {
    int i = blockIdx.x * 256 + threadIdx.x;
    if (i >= n4) return;
    split4(s, h, l, i);
}

__global__ __launch_bounds__(256)
void split6_kernel(const float* __restrict__ x, const float* __restrict__ Wq,
                   const float* __restrict__ Wk, const float* __restrict__ Wv,
                   const float* __restrict__ pek, const float* __restrict__ pev,
                   __nv_bfloat16* __restrict__ xh, __nv_bfloat16* __restrict__ xl,
                   __nv_bfloat16* __restrict__ wqh, __nv_bfloat16* __restrict__ wql,
                   __nv_bfloat16* __restrict__ wkh, __nv_bfloat16* __restrict__ wkl,
                   __nv_bfloat16* __restrict__ wvh, __nv_bfloat16* __restrict__ wvl,
                   __nv_bfloat16* __restrict__ pkh, __nv_bfloat16* __restrict__ pkl,
                   __nv_bfloat16* __restrict__ pvh, __nv_bfloat16* __restrict__ pvl) {
    int blk = blockIdx.x;
    const float* s; __nv_bfloat16 *h, *l; int i, n4;
    if (blk < 4096)      { s = x;   h = xh;  l = xl;  i = blk * 256 + threadIdx.x; n4 = 1048576; }
    else if (blk < 5120) { s = Wq;  h = wqh; l = wql; i = (blk - 4096) * 256 + threadIdx.x; n4 = 262144; }
    else if (blk < 6144) { s = Wk;  h = wkh; l = wkl; i = (blk - 5120) * 256 + threadIdx.x; n4 = 262144; }
    else if (blk < 7168) { s = Wv;  h = wvh; l = wvl; i = (blk - 6144) * 256 + threadIdx.x; n4 = 262144; }
    else if (blk < 7297) { s = pek; h = pkh; l = pkl; i = (blk - 7168) * 256 + threadIdx.x; n4 = 32784; }
    else                 { s = pev; h = pvh; l = pvl; i = (blk - 7297) * 256 + threadIdx.x; n4 = 32784; }
    if (i >= n4) return;
    split4(s, h, l, i);
}

// ---------------------------------------------------------------------------
// GEMM core (device inline): 256 threads, warp grid 2(m) x 4(n), tile 64x32.
// Pass-major MMA order (16 independent MMAs between dependent pairs).
// __launch_bounds__(256,2) on callers -> 2 CTAs/SM (smem 80KB x2 fits).
// ---------------------------------------------------------------------------
#define GKDIM 1024
#define NIT 32
#define TILE_B 10240
#define STAGE_B (4 * TILE_B)
#define GEMM_SMEM (2 * STAGE_B)

__device__ __forceinline__
void gemm_body(char* sm, uint32_t smb,
               const __nv_bfloat16* Ah, const __nv_bfloat16* Al,
               const __nv_bfloat16* Bh, const __nv_bfloat16* Bl,
               int m0, int n0,
               float* C, __nv_bfloat16* Ch, __nv_bfloat16* Cl) {
    const int tid = threadIdx.x;
    const int wid = tid >> 5, lane = tid & 31;
    const int wm = wid & 1, wn = wid >> 1;

    const __nv_bfloat16* srcs[4] = {
        Ah + (size_t)m0 * GKDIM, Al + (size_t)m0 * GKDIM,
        Bh + (size_t)n0 * GKDIM, Bl + (size_t)n0 * GKDIM };

    auto stage_load = [&](int kc, int s) {
#pragma unroll
        for (int rep = 0; rep < 8; ++rep) {
            int idx = tid + rep * 256;
            int tile = idx >> 9;
            int r = (idx >> 2) & 127;
            int c = idx & 3;
            const void* gp = srcs[tile] + (size_t)r * GKDIM + kc * 32 + c * 8;
            uint32_t dp = smb + s * STAGE_B + tile * TILE_B + r * 80 + c * 16;
            CP16(dp, gp);
        }
        asm volatile("cp.async.commit_group;");
    };

    float acc[4][4][4];
#pragma unroll
    for (int i = 0; i < 4; ++i)
#pragma unroll
        for (int j = 0; j < 4; ++j)
#pragma unroll
            for (int k = 0; k < 4; ++k) acc[i][j][k] = 0.f;

    stage_load(0, 0);

    for (int it = 0; it < NIT; ++it) {
        if (it + 1 < NIT) {
            stage_load(it + 1, (it + 1) & 1);
            asm volatile("cp.async.wait_group 1;");
        } else {
            asm volatile("cp.async.wait_group 0;");
        }
        __syncthreads();

        const uint32_t base = smb + (it & 1) * STAGE_B;
        const uint32_t aHb = base, aLb = base + TILE_B;
        const uint32_t bHb = base + 2 * TILE_B, bLb = base + 3 * TILE_B;
        const int arow = wm * 64 + (lane & 15);
        const int acolb = (lane & 16) >> 1;
        const int brow = wn * 32 + (lane & 7);
        const int bcolb = lane & 8;

#pragma unroll
        for (int k16 = 0; k16 < 32; k16 += 16) {
            uint32_t ah[4][4], al[4][4], bh[4][2], bl[4][2];
#pragma unroll
            for (int mi = 0; mi < 4; ++mi) {
                uint32_t ad = aHb + ((arow + mi * 16) * 40 + k16 + acolb) * 2;
                LDSM4(ah[mi][0], ah[mi][1], ah[mi][2], ah[mi][3], ad);
                uint32_t ad2 = aLb + ((arow + mi * 16) * 40 + k16 + acolb) * 2;
                LDSM4(al[mi][0], al[mi][1], al[mi][2], al[mi][3], ad2);
            }
#pragma unroll
            for (int ni = 0; ni < 4; ++ni) {
                uint32_t bd = bHb + ((brow + ni * 8) * 40 + k16 + bcolb) * 2;
                asm volatile("ldmatrix.sync.aligned.m8n8.x2.shared.b16 {%0,%1}, [%2];"
                             : "=r"(bh[ni][0]), "=r"(bh[ni][1]) : "r"(bd));
                uint32_t bd2 = bLb + ((brow + ni * 8) * 40 + k16 + bcolb) * 2;
                asm volatile("ldmatrix.sync.aligned.m8n8.x2.shared.b16 {%0,%1}, [%2];"
                             : "=r"(bl[ni][0]), "=r"(bl[ni][1]) : "r"(bd2));
            }
            // pass-major: dependent MMAs on one acc are 16 issues apart
#pragma unroll
            for (int mi = 0; mi < 4; ++mi)
#pragma unroll
                for (int ni = 0; ni < 4; ++ni)
                    MMA_OP(acc[mi][ni], ah[mi], bh[ni]);
#pragma unroll
            for (int mi = 0; mi < 4; ++mi)
#pragma unroll
                for (int ni = 0; ni < 4; ++ni)
                    MMA_OP(acc[mi][ni], ah[mi], bl[ni]);
#pragma unroll
            for (int mi = 0; mi < 4; ++mi)
#pragma unroll
                for (int ni = 0; ni < 4; ++ni)
                    MMA_OP(acc[mi][ni], al[mi], bh[ni]);
        }
        __syncthreads();
    }

    const int crow = m0 + wm * 64 + (lane >> 2);
    const int ccol = n0 + wn * 32 + (lane & 3) * 2;
    if (Ch) {
#pragma unroll
        for (int mi = 0; mi < 4; ++mi)
#pragma unroll
            for (int ni = 0; ni < 4; ++ni) {
                size_t r0 = (size_t)(crow + mi * 16) * DD + ccol + ni * 8;
                size_t r1 = (size_t)(crow + mi * 16 + 8) * DD + ccol + ni * 8;
#pragma unroll
                for (int half = 0; half < 2; ++half) {
                    float v0 = acc[mi][ni][half * 2], v1 = acc[mi][ni][half * 2 + 1];
                    __nv_bfloat16 h0 = __float2bfloat16(v0), h1 = __float2bfloat16(v1);
                    __nv_bfloat16 q0b = __float2bfloat16(v0 - __bfloat162float(h0));
                    __nv_bfloat16 q1b = __float2bfloat16(v1 - __bfloat162float(h1));
                    size_t r = half ? r1 : r0;
                    *(uint32_t*)&Ch[r] = pack2(h0, h1);
                    *(uint32_t*)&Cl[r] = pack2(q0b, q1b);
                }
            }
    } else {
#pragma unroll
        for (int mi = 0; mi < 4; ++mi)
#pragma unroll
            for (int ni = 0; ni < 4; ++ni) {
                size_t r0 = (size_t)(crow + mi * 16) * DD + ccol + ni * 8;
                size_t r1 = (size_t)(crow + mi * 16 + 8) * DD + ccol + ni * 8;
                *(float2*)&C[r0] = make_float2(acc[mi][ni][0], acc[mi][ni][1]);
                *(float2*)&C[r1] = make_float2(acc[mi][ni][2], acc[mi][ni][3]);
            }
    }
}

// Single GEMM (used for the Wo output projection, fp32 out)
__global__ __launch_bounds__(256, 2)
void gemm_mma(const __nv_bfloat16* __restrict__ Ah, const __nv_bfloat16* __restrict__ Al,
              const __nv_bfloat16* __restrict__ Bh, const __nv_bfloat16* __restrict__ Bl,
              float* __restrict__ C,
              __nv_bfloat16* __restrict__ Ch, __nv_bfloat16* __restrict__ Cl) {
    extern __shared__ __align__(128) char sm[];
    gemm_body(sm, smem_u32(sm), Ah, Al, Bh, Bl,
              blockIdx.y * 128, blockIdx.x * 128, C, Ch, Cl);
}

// Fused Q/K/V projection: grid (24, 32); blockIdx.x>>3 selects the matrix.
__global__ __launch_bounds__(256, 2)
void gemm_qkv(const __nv_bfloat16* __restrict__ Ah, const __nv_bfloat16* __restrict__ Al,
              const __nv_bfloat16* __restrict__ Bh0, const __nv_bfloat16* __restrict__ Bl0,
              const __nv_bfloat16* __restrict__ Bh1, const __nv_bfloat16* __restrict__ Bl1,
              const __nv_bfloat16* __restrict__ Bh2, const __nv_bfloat16* __restrict__ Bl2,
              __nv_bfloat16* __restrict__ Ch0, __nv_bfloat16* __restrict__ Cl0,
              __nv_bfloat16* __restrict__ Ch1, __nv_bfloat16* __restrict__ Cl1,
              __nv_bfloat16* __restrict__ Ch2, __nv_bfloat16* __restrict__ Cl2) {
    extern __shared__ __align__(128) char sm[];
    int sel = blockIdx.x >> 3;
    int n0 = (blockIdx.x & 7) * 128;
    const __nv_bfloat16* Bh = (sel == 0) ? Bh0 : (sel == 1) ? Bh1 : Bh2;
    const __nv_bfloat16* Bl = (sel == 0) ? Bl0 : (sel == 1) ? Bl1 : Bl2;
    __nv_bfloat16* Ch = (sel == 0) ? Ch0 : (sel == 1) ? Ch1 : Ch2;
    __nv_bfloat16* Cl = (sel == 0) ? Cl0 : (sel == 1) ? Cl1 : Cl2;
    gemm_body(sm, smem_u32(sm), Ah, Al, Bh, Bl,
              blockIdx.y * 128, n0, nullptr, Ch, Cl);
}

// ---------------------------------------------------------------------------
// Fused flash attention, 256 threads, warp grid 4(q) x 2(n).  (unchanged R11)
// ---------------------------------------------------------------------------
#define AQH   0
#define AQL   9216
#define AKH   18432
#define AKL   27648
#define AVH   36864
#define AVL   46080
#define AEKH  55296
#define AEKL  73728
#define AEVH  92160
#define AEVL  110592
#define AU    129024
#define APH   162816
#define APL   172032
#define ASBUF 162816
#define APDH  181248
#define APDL  198656
#define ASTAT 216064
#define ATTN_SMEM (216064 + 768)

__global__ __launch_bounds__(256)
void attn_fused(const __nv_bfloat16* __restrict__ Qh, const __nv_bfloat16* __restrict__ Ql,
                const __nv_bfloat16* __restrict__ Kh, const __nv_bfloat16* __restrict__ Kl,
                const __nv_bfloat16* __restrict__ Vh, const __nv_bfloat16* __restrict__ Vl,
                const __nv_bfloat16* __restrict__ Ekh, const __nv_bfloat16* __restrict__ Ekl,
                const __nv_bfloat16* __restrict__ Evh, const __nv_bfloat16* __restrict__ Evl,
                __nv_bfloat16* __restrict__ Oh, __nv_bfloat16* __restrict__ Ol) {
    extern __shared__ __align__(128) char sm[];
    const uint32_t smb = smem_u32(sm);
    const int qt = 15 - blockIdx.x;
    const int q0 = qt * 64;
    const int bh = blockIdx.y;
    const int b = bh >> 4, h = bh & 15;
    const int tid = threadIdx.x;
    const int wid = tid >> 5, lane = tid & 31;
    const int wq = wid & 3, wn = wid >> 2;
    const int frow = lane & 15;
    const int fcolb = (lane >> 4) << 3;
    const int crow = wq * 16 + (lane >> 2);
    const int ccol = (lane & 3) * 2;
    const int srow = tid >> 2, spart = tid & 3;

    float* mS = (float*)(sm + ASTAT);
    float* lS = mS + 64;
    float* fS = mS + 128;
    float* Us = (float*)(sm + AU);
    float* Sb = (float*)(sm + ASBUF);

    if (tid < 64) { mS[tid] = -1e30f; lS[tid] = 0.f; }

    {
        const __nv_bfloat16* gq = Qh + (size_t)(b * LL + q0) * DD + h * HD;
        const __nv_bfloat16* gql = Ql + (size_t)(b * LL + q0) * DD + h * HD;
#pragma unroll
        for (int t = 0; t < 4; ++t) {
            int i = tid + t * 256;
            int tt = i >> 9;
            int r = (i >> 3) & 63;
            int c = i & 7;
            const __nv_bfloat16* sp = (tt ? gql : gq) + (size_t)r * DD + c * 8;
            CP16(smb + (tt ? AQL : AQH) + r * 144 + c * 16, sp);
        }
    }

    float acc[4][4];
#pragma unroll
    for (int i = 0; i < 4; ++i)
#pragma unroll
        for (int j = 0; j < 4; ++j) acc[i][j] = 0.f;

    for (int k0 = 0; k0 <= q0; k0 += 64) {
        const int base = k0 - q0 + 961;
        const bool first = (k0 == 0);
        __syncthreads();
        {
            const __nv_bfloat16* g0 = Kh + (size_t)(b * LL + k0) * DD + h * HD;
            const __nv_bfloat16* g1 = Kl + (size_t)(b * LL + k0) * DD + h * HD;
            const __nv_bfloat16* g2 = Vh + (size_t)(b * LL + k0) * DD + h * HD;
            const __nv_bfloat16* g3 = Vl + (size_t)(b * LL + k0) * DD + h * HD;
#pragma unroll
            for (int t = 0; t < 8; ++t) {
                int i = tid + t * 256;
                int tile = i >> 9;
                int r = (i >> 3) & 63;
                int c = i & 7;
                const __nv_bfloat16* sp =
                    ((tile == 0) ? g0 : (tile == 1) ? g1 : (tile == 2) ? g2 : g3)
                    + (size_t)r * DD + c * 8;
                uint32_t off = (tile == 0) ? AKH : (tile == 1) ? AKL : (tile == 2) ? AVH : AVL;
                CP16(smb + off + r * 144 + c * 16, sp);
            }
        }
        {
            int g0r = base + (first ? 0 : 64);
            int nt = first ? 16 : 8;
            int rsh = first ? 10 : 9;
            int rmask = first ? 127 : 63;
            for (int t = 0; t < nt; ++t) {
                int i = tid + t * 256;
                int tile = i >> rsh;
                int rr = (i >> 3) & rmask;
                int c = i & 7;
                int g = g0r + rr;
                const __nv_bfloat16* sp =
                    ((tile == 0) ? Ekh : (tile == 1) ? Ekl : (tile == 2) ? Evh : Evl)
                    + (size_t)g * HD + c * 8;
                uint32_t off = (tile == 0) ? AEKH : (tile == 1) ? AEKL
                             : (tile == 2) ? AEVH : AEVL;
                CP16(smb + off + (uint32_t)(g & 127) * 144 + c * 16, sp);
            }
        }
        CPWAIT();
        __syncthreads();

        {
            float aqk[4][4], au[8][4];
#pragma unroll
            for (int i = 0; i < 4; ++i)
#pragma unroll
                for (int j = 0; j < 4; ++j) aqk[i][j] = 0.f;
#pragma unroll
            for (int i = 0; i < 8; ++i)
#pragma unroll
                for (int j = 0; j < 4; ++j) au[i][j] = 0.f;

#pragma unroll
            for (int d16 = 0; d16 < 64; d16 += 16) {
                uint32_t ah[4], al[4];
                LDSM4(ah[0], ah[1], ah[2], ah[3],
                      smb + AQH + (wq * 16 + frow) * 144 + (d16 + fcolb) * 2);
                LDSM4(al[0], al[1], al[2], al[3],
                      smb + AQL + (wq * 16 + frow) * 144 + (d16 + fcolb) * 2);
#pragma unroll
                for (int ngl = 0; ngl < 2; ++ngl) {
                    int ng = wn * 2 + ngl;
                    uint32_t kh4[4], kl4[4];
                    LDSM4(kh4[0], kh4[1], kh4[2], kh4[3],
                          smb + AKH + (ng * 16 + frow) * 144 + (d16 + fcolb) * 2);
                    LDSM4(kl4[0], kl4[1], kl4[2], kl4[3],
                          smb + AKL + (ng * 16 + frow) * 144 + (d16 + fcolb) * 2);
                    uint32_t f0h[2] = {kh4[0], kh4[2]}, f1h[2] = {kh4[1], kh4[3]};
                    uint32_t f0l[2] = {kl4[0], kl4[2]}, f1l[2] = {kl4[1], kl4[3]};
                    MMA_OP(aqk[2 * ngl],     ah, f0h);
                    MMA_OP(aqk[2 * ngl],     ah, f0l);
                    MMA_OP(aqk[2 * ngl],     al, f0h);
                    MMA_OP(aqk[2 * ngl + 1], ah, f1h);
                    MMA_OP(aqk[2 * ngl + 1], ah, f1l);
                    MMA_OP(aqk[2 * ngl + 1], al, f1h);
                }
                if (first) {
#pragma unroll
                    for (int ngl = 0; ngl < 4; ++ngl) {
                        int lr = (wn * 4 + ngl) * 16;
                        uint32_t e4h[4], e4l[4];
                        uint32_t ra = (uint32_t)((base + lr + frow) & 127) * 144 + (d16 + fcolb) * 2;
                        LDSM4(e4h[0], e4h[1], e4h[2], e4h[3], smb + AEKH + ra);
                        LDSM4(e4l[0], e4l[1], e4l[2], e4l[3], smb + AEKL + ra);
                        uint32_t f0h[2] = {e4h[0], e4h[2]}, f1h[2] = {e4h[1], e4h[3]};
                        uint32_t f0l[2] = {e4l[0], e4l[2]}, f1l[2] = {e4l[1], e4l[3]};
                        MMA_OP(au[2 * ngl],     ah, f0h);
                        MMA_OP(au[2 * ngl],     ah, f0l);
                        MMA_OP(au[2 * ngl],     al, f0h);
                        MMA_OP(au[2 * ngl + 1], ah, f1h);
                        MMA_OP(au[2 * ngl + 1], ah, f1l);
                        MMA_OP(au[2 * ngl + 1], al, f1h);
                    }
                } else {
#pragma unroll
                    for (int ngl = 0; ngl < 2; ++ngl) {
                        int lr = 64 + (wn * 2 + ngl) * 16;
                        uint32_t e4h[4], e4l[4];
                        uint32_t ra = (uint32_t)((base + lr + frow) & 127) * 144 + (d16 + fcolb) * 2;
                        LDSM4(e4h[0], e4h[1], e4h[2], e4h[3], smb + AEKH + ra);
                        LDSM4(e4l[0], e4l[1], e4l[2], e4l[3], smb + AEKL + ra);
                        uint32_t f0h[2] = {e4h[0], e4h[2]}, f1h[2] = {e4h[1], e4h[3]};
                        uint32_t f0l[2] = {e4l[0], e4l[2]}, f1l[2] = {e4l[1], e4l[3]};
                        MMA_OP(au[2 * ngl],     ah, f0h);
                        MMA_OP(au[2 * ngl],     ah, f0l);
                        MMA_OP(au[2 * ngl],     al, f0h);
                        MMA_OP(au[2 * ngl + 1], ah, f1h);
                        MMA_OP(au[2 * ngl + 1], ah, f1l);
                        MMA_OP(au[2 * ngl + 1], al, f1h);
                    }
                }
            }
#pragma unroll
            for (int ia = 0; ia < 4; ++ia) {
                int kcol = (wn * 2 + (ia >> 1)) * 16 + (ia & 1) * 8 + ccol;
                Sb[crow * 68 + kcol]           = aqk[ia][0];
                Sb[crow * 68 + kcol + 1]       = aqk[ia][1];
                Sb[(crow + 8) * 68 + kcol]     = aqk[ia][2];
                Sb[(crow + 8) * 68 + kcol + 1] = aqk[ia][3];
            }
            int cnt = first ? 8 : 4;
            for (int ia = 0; ia < cnt; ++ia) {
                int lr = (first ? (wn * 4 + (ia >> 1)) * 16
                                : 64 + (wn * 2 + (ia >> 1)) * 16) + (ia & 1) * 8 + ccol;
                int p0 = (base + lr) & 127;
                int p1 = (base + lr + 1) & 127;
                Us[crow * 132 + p0]       = au[ia][0];
                Us[crow * 132 + p1]       = au[ia][1];
                Us[(crow + 8) * 132 + p0] = au[ia][2];
                Us[(crow + 8) * 132 + p1] = au[ia][3];
            }
        }
        __syncthreads();

        float p[16];
        {
            int qg = q0 + srow;
            float mx = -1e30f;
#pragma unroll
            for (int j = 0; j < 16; ++j) {
                int c = spart * 16 + j;
                int pc = (base + c - srow + 63) & 127;
                float s = (Sb[srow * 68 + c] + Us[srow * 132 + pc]) * 0.125f;
                if (k0 + c > qg) s = -1e30f;
                p[j] = s;
                mx = fmaxf(mx, s);
            }
            mx = fmaxf(mx, __shfl_xor_sync(0xffffffffu, mx, 1));
            mx = fmaxf(mx, __shfl_xor_sync(0xffffffffu, mx, 2));
            float mold = mS[srow];
            float mnew = fmaxf(mold, mx);
            float fct = __expf(mold - mnew);
            float rs = 0.f;
#pragma unroll
            for (int j = 0; j < 16; ++j) { p[j] = __expf(p[j] - mnew); rs += p[j]; }
            rs += __shfl_xor_sync(0xffffffffu, rs, 1);
            rs += __shfl_xor_sync(0xffffffffu, rs, 2);
            if (spart == 0) {
                mS[srow] = mnew;
                lS[srow] = lS[srow] * fct + rs;
                fS[srow] = fct;
            }
        }
        __syncthreads();

#pragma unroll
        for (int j2 = 0; j2 < 8; ++j2) {
            int c = spart * 16 + j2 * 2;
            float v0 = p[j2 * 2], v1 = p[j2 * 2 + 1];
            __nv_bfloat16 h0 = __float2bfloat16(v0), h1 = __float2bfloat16(v1);
            __nv_bfloat16 l0 = __float2bfloat16(v0 - __bfloat162float(h0));
            __nv_bfloat16 l1 = __float2bfloat16(v1 - __bfloat162float(h1));
            *(uint32_t*)(sm + APH + srow * 144 + c * 2) = pack2(h0, h1);
            *(uint32_t*)(sm + APL + srow * 144 + c * 2) = pack2(l0, l1);
            __nv_bfloat16 hs[2] = {h0, h1}, ls[2] = {l0, l1};
#pragma unroll
            for (int cc = 0; cc < 2; ++cc) {
                int r = c + cc - srow + 63;
                *(uint16_t*)(sm + APDH + srow * 272 + r * 2) = bf16bits(hs[cc]);
                *(uint16_t*)(sm + APDL + srow * 272 + r * 2) = bf16bits(ls[cc]);
                int rz = (r + 64) & 127;
                *(uint16_t*)(sm + APDH + srow * 272 + rz * 2) = 0;
                *(uint16_t*)(sm + APDL + srow * 272 + rz * 2) = 0;
            }
        }
        {
            float f0 = fS[crow], f1 = fS[crow + 8];
#pragma unroll
            for (int ni = 0; ni < 4; ++ni) {
                acc[ni][0] *= f0; acc[ni][1] *= f0;
                acc[ni][2] *= f1; acc[ni][3] *= f1;
            }
        }
        __syncthreads();

#pragma unroll
        for (int k16 = 0; k16 < 64; k16 += 16) {
            uint32_t ph[4], pl[4];
            LDSM4(ph[0], ph[1], ph[2], ph[3],
                  smb + APH + (wq * 16 + frow) * 144 + (k16 + fcolb) * 2);
            LDSM4(pl[0], pl[1], pl[2], pl[3],
                  smb + APL + (wq * 16 + frow) * 144 + (k16 + fcolb) * 2);
#pragma unroll
            for (int ngl = 0; ngl < 2; ++ngl) {
                int ng = wn * 2 + ngl;
                uint32_t vh4[4], vl4[4];
                LDSM4T(vh4[0], vh4[1], vh4[2], vh4[3],
                       smb + AVH + (k16 + frow) * 144 + (ng * 16 + fcolb) * 2);
                LDSM4T(vl4[0], vl4[1], vl4[2], vl4[3],
                       smb + AVL + (k16 + frow) * 144 + (ng * 16 + fcolb) * 2);
                uint32_t f0h[2] = {vh4[0], vh4[1]}, f1h[2] = {vh4[2], vh4[3]};
                uint32_t f0l[2] = {vl4[0], vl4[1]}, f1l[2] = {vl4[2], vl4[3]};
                MMA_OP(acc[2 * ngl],     ph, f0h);
                MMA_OP(acc[2 * ngl],     ph, f0l);
                MMA_OP(acc[2 * ngl],     pl, f0h);
                MMA_OP(acc[2 * ngl + 1], ph, f1h);
                MMA_OP(acc[2 * ngl + 1], ph, f1l);
                MMA_OP(acc[2 * ngl + 1], pl, f1h);
            }
        }
        {
            const int rs0 = 48 - wq * 16;
#pragma unroll
            for (int k5 = 0; k5 < 5; ++k5) {
                int r16 = rs0 + k5 * 16;
                uint32_t ph[4], pl[4];
                LDSM4(ph[0], ph[1], ph[2], ph[3],
                      smb + APDH + (wq * 16 + frow) * 272 + (r16 + fcolb) * 2);
                LDSM4(pl[0], pl[1], pl[2], pl[3],
                      smb + APDL + (wq * 16 + frow) * 272 + (r16 + fcolb) * 2);
#pragma unroll
                for (int ngl = 0; ngl < 2; ++ngl) {
                    int ng = wn * 2 + ngl;
                    uint32_t eh4[4], el4[4];
                    uint32_t ra = (uint32_t)((base + r16 + frow) & 127) * 144 + (ng * 16 + fcolb) * 2;
                    LDSM4T(eh4[0], eh4[1], eh4[2], eh4[3], smb + AEVH + ra);
                    LDSM4T(el4[0], el4[1], el4[2], el4[3], smb + AEVL + ra);
                    uint32_t f0h[2] = {eh4[0], eh4[1]}, f1h[2] = {eh4[2], eh4[3]};
                    uint32_t f0l[2] = {el4[0], el4[1]}, f1l[2] = {el4[2], el4[3]};
                    MMA_OP(acc[2 * ngl],     ph, f0h);
                    MMA_OP(acc[2 * ngl],     ph, f0l);
                    MMA_OP(acc[2 * ngl],     pl, f0h);
                    MMA_OP(acc[2 * ngl + 1], ph, f1h);
                    MMA_OP(acc[2 * ngl + 1], ph, f1l);
                    MMA_OP(acc[2 * ngl + 1], pl, f1h);
                }
            }
        }
    }

    float inv0 = 1.f / lS[crow];
    float inv1 = 1.f / lS[crow + 8];
    __nv_bfloat16* Ogh = Oh + (size_t)(b * LL + q0) * DD + h * HD;
    __nv_bfloat16* Ogl = Ol + (size_t)(b * LL + q0) * DD + h * HD;
#pragma unroll
    for (int ia = 0; ia < 4; ++ia) {
        int col = wn * 32 + (ia >> 1) * 16 + (ia & 1) * 8 + ccol;
#pragma unroll
        for (int hf = 0; hf < 2; ++hf) {
            float v0 = acc[ia][hf * 2]     * (hf ? inv1 : inv0);
            float v1 = acc[ia][hf * 2 + 1] * (hf ? inv1 : inv0);
            __nv_bfloat16 h0 = __float2bfloat16(v0), h1 = __float2bfloat16(v1);
            __nv_bfloat16 l0 = __float2bfloat16(v0 - __bfloat162float(h0));
            __nv_bfloat16 l1 = __float2bfloat16(v1 - __bfloat162float(h1));
            size_t off = (size_t)(crow + hf * 8) * DD + col;
            *(uint32_t*)&Ogh[off] = pack2(h0, h1);
            *(uint32_t*)&Ogl[off] = pack2(l0, l1);
        }
    }
}

// ---------------------------------------------------------------------------
// Launch
// ---------------------------------------------------------------------------
extern "C" void kernel_launch(void* const* d_in, const int* in_sizes, int n_in,
                              void* d_out, int out_size) {
    const float* x   = (const float*)d_in[0];
    const float* Wq  = (const float*)d_in[1];
    const float* Wk  = (const float*)d_in[2];
    const float* Wv  = (const float*)d_in[3];
    const float* Wo  = (const float*)d_in[4];
    const float* pek = (const float*)d_in[5];
    const float* pev = (const float*)d_in[6];
    float* out = (float*)d_out;

    __nv_bfloat16 *xh, *xl, *wh, *wl, *wqh, *wql, *wkh, *wkl, *wvh, *wvl;
    __nv_bfloat16 *Qh, *Ql, *Kh, *Kl, *Vh, *Vl, *Oh, *Ol;
    __nv_bfloat16 *pekh, *pekl, *pevh, *pevl;
    cudaGetSymbolAddress((void**)&xh, g_xh);
    cudaGetSymbolAddress((void**)&xl, g_xl);
    cudaGetSymbolAddress((void**)&wh, g_wh);
    cudaGetSymbolAddress((void**)&wl, g_wl);
    cudaGetSymbolAddress((void**)&wqh, g_wqh);
    cudaGetSymbolAddress((void**)&wql, g_wql);
    cudaGetSymbolAddress((void**)&wkh, g_wkh);
    cudaGetSymbolAddress((void**)&wkl, g_wkl);
    cudaGetSymbolAddress((void**)&wvh, g_wvh);
    cudaGetSymbolAddress((void**)&wvl, g_wvl);
    cudaGetSymbolAddress((void**)&Qh, g_Qh);
    cudaGetSymbolAddress((void**)&Ql, g_Ql);
    cudaGetSymbolAddress((void**)&Kh, g_Kh);
    cudaGetSymbolAddress((void**)&Kl, g_Kl);
    cudaGetSymbolAddress((void**)&Vh, g_Vh);
    cudaGetSymbolAddress((void**)&Vl, g_Vl);
    cudaGetSymbolAddress((void**)&Oh, g_Oh);
    cudaGetSymbolAddress((void**)&Ol, g_Ol);
    cudaGetSymbolAddress((void**)&pekh, g_pekh);
    cudaGetSymbolAddress((void**)&pekl, g_pekl);
    cudaGetSymbolAddress((void**)&pevh, g_pevh);
    cudaGetSymbolAddress((void**)&pevl, g_pevl);

    cudaFuncSetAttribute(gemm_mma, cudaFuncAttributeMaxDynamicSharedMemorySize, GEMM_SMEM);
    cudaFuncSetAttribute(gemm_qkv, cudaFuncAttributeMaxDynamicSharedMemorySize, GEMM_SMEM);
    cudaFuncSetAttribute(attn_fused, cudaFuncAttributeMaxDynamicSharedMemorySize, ATTN_SMEM);

    const int n4w = DD * DD / 4;
    dim3 ggemm(DD / 128, MROWS / 128);
    dim3 gqkv(3 * DD / 128, MROWS / 128);   // (24, 32)

    split6_kernel<<<7426, 256>>>(x, Wq, Wk, Wv, pek, pev,
                                 xh, xl, wqh, wql, wkh, wkl, wvh, wvl,
                                 pekh, pekl, pevh, pevl);
    gemm_qkv<<<gqkv, 256, GEMM_SMEM>>>(xh, xl, wqh, wql, wkh, wkl, wvh, wvl,
                                       Qh, Ql, Kh, Kl, Vh, Vl);
    split_kernel<<<(n4w + 255) / 256, 256>>>(Wo, wh, wl, n4w);
    attn_fused<<<dim3(16, 64), 256, ATTN_SMEM>>>(Qh, Ql, Kh, Kl, Vh, Vl,
                                                 pekh, pekl, pevh, pevl, Oh, Ol);
    gemm_mma<<<ggemm, 256, GEMM_SMEM>>>(Oh, Ol, wh, wl, out, nullptr, nullptr);
}

// round 14
// speedup vs baseline: 1.1541x; 1.0477x over previous
#include <cuda_runtime.h>
#include <cuda_bf16.h>
#include <cstdint>

// Problem constants
#define BB 4
#define LL 1024
#define DD 1024
#define HH 16
#define HD 64
#define MROWS 4096           // B*L
#define PEN 2049

// Scratch (device globals; allocation is forbidden)
__device__ __nv_bfloat16 g_xh[MROWS * DD];
__device__ __nv_bfloat16 g_xl[MROWS * DD];
__device__ __nv_bfloat16 g_wqh[DD * DD];
__device__ __nv_bfloat16 g_wql[DD * DD];
__device__ __nv_bfloat16 g_wkh[DD * DD];
__device__ __nv_bfloat16 g_wkl[DD * DD];
__device__ __nv_bfloat16 g_wvh[DD * DD];
__device__ __nv_bfloat16 g_wvl[DD * DD];
__device__ __nv_bfloat16 g_wh[DD * DD];
__device__ __nv_bfloat16 g_wl[DD * DD];
__device__ __nv_bfloat16 g_Qh[MROWS * DD];
__device__ __nv_bfloat16 g_Ql[MROWS * DD];
__device__ __nv_bfloat16 g_Kh[MROWS * DD];
__device__ __nv_bfloat16 g_Kl[MROWS * DD];
__device__ __nv_bfloat16 g_Vh[MROWS * DD];
__device__ __nv_bfloat16 g_Vl[MROWS * DD];
__device__ __nv_bfloat16 g_Oh[MROWS * DD];
__device__ __nv_bfloat16 g_Ol[MROWS * DD];
__device__ __nv_bfloat16 g_pekh[PEN * HD];
__device__ __nv_bfloat16 g_pekl[PEN * HD];
__device__ __nv_bfloat16 g_pevh[PEN * HD];
__device__ __nv_bfloat16 g_pevl[PEN * HD];

__device__ __forceinline__ uint32_t smem_u32(const void* p) {
    uint32_t a;
    asm("{ .reg .u64 t; cvta.to.shared.u64 t, %1; cvt.u32.u64 %0, t; }" : "=r"(a) : "l"(p));
    return a;
}

#define MMA_OP(c, af, bf) \
    asm volatile("mma.sync.aligned.m16n8k16.row.col.f32.bf16.bf16.f32 " \
                 "{%0,%1,%2,%3}, {%4,%5,%6,%7}, {%8,%9}, {%0,%1,%2,%3};" \
                 : "+f"((c)[0]), "+f"((c)[1]), "+f"((c)[2]), "+f"((c)[3]) \
                 : "r"((af)[0]), "r"((af)[1]), "r"((af)[2]), "r"((af)[3]), \
                   "r"((bf)[0]), "r"((bf)[1]))

#define LDSM4(d0,d1,d2,d3,a) \
    asm volatile("ldmatrix.sync.aligned.m8n8.x4.shared.b16 {%0,%1,%2,%3}, [%4];" \
                 : "=r"(d0), "=r"(d1), "=r"(d2), "=r"(d3) : "r"(a))
#define LDSM4T(d0,d1,d2,d3,a) \
    asm volatile("ldmatrix.sync.aligned.m8n8.x4.trans.shared.b16 {%0,%1,%2,%3}, [%4];" \
                 : "=r"(d0), "=r"(d1), "=r"(d2), "=r"(d3) : "r"(a))

#define CP16(dst, src) \
    asm volatile("cp.async.cg.shared.global [%0], [%1], 16;" :: "r"(dst), "l"(src))
#define CPWAIT() \
    asm volatile("cp.async.commit_group;\n\tcp.async.wait_group 0;" ::: "memory")

__device__ __forceinline__ uint32_t pack2(__nv_bfloat16 a, __nv_bfloat16 b) {
    __nv_bfloat162 t(a, b);
    return *reinterpret_cast<uint32_t*>(&t);
}
__device__ __forceinline__ uint16_t bf16bits(__nv_bfloat16 h) {
    return *reinterpret_cast<uint16_t*>(&h);
}

// ---------------------------------------------------------------------------
// fp32 -> bf16 hi/lo split
// ---------------------------------------------------------------------------
__device__ __forceinline__ void split4(const float* s, __nv_bfloat16* h,
                                       __nv_bfloat16* l, int i) {
    float4 v = ((const float4*)s)[i];
    __nv_bfloat16 h0 = __float2bfloat16(v.x);
    __nv_bfloat16 h1 = __float2bfloat16(v.y);
    __nv_bfloat16 h2 = __float2bfloat16(v.z);
    __nv_bfloat16 h3 = __float2bfloat16(v.w);
    __nv_bfloat16 l0 = __float2bfloat16(v.x - __bfloat162float(h0));
    __nv_bfloat16 l1 = __float2bfloat16(v.y - __bfloat162float(h1));
    __nv_bfloat16 l2 = __float2bfloat16(v.z - __bfloat162float(h2));
    __nv_bfloat16 l3 = __float2bfloat16(v.w - __bfloat162float(h3));
    ((uint2*)h)[i] = make_uint2(pack2(h0, h1), pack2(h2, h3));
    ((uint2*)l)[i] = make_uint2(pack2(l0, l1), pack2(l2, l3));
}

__global__ __launch_bounds__(256)
void split_kernel(const float* __restrict__ s, __nv_bfloat16* __restrict__ h,
                  __nv_bfloat16* __restrict__ l, int n4) {
    int i = blockIdx.x * 256 + threadIdx.x;
    if (i >= n4) return;
    split4(s, h, l, i);
}

__global__ __launch_bounds__(256)
void split6_kernel(const float* __restrict__ x, const float* __restrict__ Wq,
                   const float* __restrict__ Wk, const float* __restrict__ Wv,
                   const float* __restrict__ pek, const float* __restrict__ pev,
                   __nv_bfloat16* __restrict__ xh, __nv_bfloat16* __restrict__ xl,
                   __nv_bfloat16* __restrict__ wqh, __nv_bfloat16* __restrict__ wql,
                   __nv_bfloat16* __restrict__ wkh, __nv_bfloat16* __restrict__ wkl,
                   __nv_bfloat16* __restrict__ wvh, __nv_bfloat16* __restrict__ wvl,
                   __nv_bfloat16* __restrict__ pkh, __nv_bfloat16* __restrict__ pkl,
                   __nv_bfloat16* __restrict__ pvh, __nv_bfloat16* __restrict__ pvl) {
    int blk = blockIdx.x;
    const float* s; __nv_bfloat16 *h, *l; int i, n4;
    if (blk < 4096)      { s = x;   h = xh;  l = xl;  i = blk * 256 + threadIdx.x; n4 = 1048576; }
    else if (blk < 5120) { s = Wq;  h = wqh; l = wql; i = (blk - 4096) * 256 + threadIdx.x; n4 = 262144; }
    else if (blk < 6144) { s = Wk;  h = wkh; l = wkl; i = (blk - 5120) * 256 + threadIdx.x; n4 = 262144; }
    else if (blk < 7168) { s = Wv;  h = wvh; l = wvl; i = (blk - 6144) * 256 + threadIdx.x; n4 = 262144; }
    else if (blk < 7297) { s = pek; h = pkh; l = pkl; i = (blk - 7168) * 256 + threadIdx.x; n4 = 32784; }
    else                 { s = pev; h = pvh; l = pvl; i = (blk - 7297) * 256 + threadIdx.x; n4 = 32784; }
    if (i >= n4) return;
    split4(s, h, l, i);
}

// ---------------------------------------------------------------------------
// GEMM core: 256 threads, warp grid 2(m) x 4(n), tile 64x32, 2 CTAs/SM.
// ---------------------------------------------------------------------------
#define GKDIM 1024
#define NIT 32
#define TILE_B 10240
#define STAGE_B (4 * TILE_B)
#define GEMM_SMEM (2 * STAGE_B)

__device__ __forceinline__
void gemm_body(char* sm, uint32_t smb,
               const __nv_bfloat16* Ah, const __nv_bfloat16* Al,
               const __nv_bfloat16* Bh, const __nv_bfloat16* Bl,
               int m0, int n0,
               float* C, __nv_bfloat16* Ch, __nv_bfloat16* Cl) {
    const int tid = threadIdx.x;
    const int wid = tid >> 5, lane = tid & 31;
    const int wm = wid & 1, wn = wid >> 1;

    const __nv_bfloat16* srcs[4] = {
        Ah + (size_t)m0 * GKDIM, Al + (size_t)m0 * GKDIM,
        Bh + (size_t)n0 * GKDIM, Bl + (size_t)n0 * GKDIM };

    auto stage_load = [&](int kc, int s) {
#pragma unroll
        for (int rep = 0; rep < 8; ++rep) {
            int idx = tid + rep * 256;
            int tile = idx >> 9;
            int r = (idx >> 2) & 127;
            int c = idx & 3;
            const void* gp = srcs[tile] + (size_t)r * GKDIM + kc * 32 + c * 8;
            uint32_t dp = smb + s * STAGE_B + tile * TILE_B + r * 80 + c * 16;
            CP16(dp, gp);
        }
        asm volatile("cp.async.commit_group;");
    };

    float acc[4][4][4];
#pragma unroll
    for (int i = 0; i < 4; ++i)
#pragma unroll
        for (int j = 0; j < 4; ++j)
#pragma unroll
            for (int k = 0; k < 4; ++k) acc[i][j][k] = 0.f;

    stage_load(0, 0);

    for (int it = 0; it < NIT; ++it) {
        if (it + 1 < NIT) {
            stage_load(it + 1, (it + 1) & 1);
            asm volatile("cp.async.wait_group 1;");
        } else {
            asm volatile("cp.async.wait_group 0;");
        }
        __syncthreads();

        const uint32_t base = smb + (it & 1) * STAGE_B;
        const uint32_t aHb = base, aLb = base + TILE_B;
        const uint32_t bHb = base + 2 * TILE_B, bLb = base + 3 * TILE_B;
        const int arow = wm * 64 + (lane & 15);
        const int acolb = (lane & 16) >> 1;
        const int brow = wn * 32 + (lane & 7);
        const int bcolb = lane & 8;

#pragma unroll
        for (int k16 = 0; k16 < 32; k16 += 16) {
            uint32_t ah[4][4], al[4][4], bh[4][2], bl[4][2];
#pragma unroll
            for (int mi = 0; mi < 4; ++mi) {
                uint32_t ad = aHb + ((arow + mi * 16) * 40 + k16 + acolb) * 2;
                LDSM4(ah[mi][0], ah[mi][1], ah[mi][2], ah[mi][3], ad);
                uint32_t ad2 = aLb + ((arow + mi * 16) * 40 + k16 + acolb) * 2;
                LDSM4(al[mi][0], al[mi][1], al[mi][2], al[mi][3], ad2);
            }
#pragma unroll
            for (int ni = 0; ni < 4; ++ni) {
                uint32_t bd = bHb + ((brow + ni * 8) * 40 + k16 + bcolb) * 2;
                asm volatile("ldmatrix.sync.aligned.m8n8.x2.shared.b16 {%0,%1}, [%2];"
                             : "=r"(bh[ni][0]), "=r"(bh[ni][1]) : "r"(bd));
                uint32_t bd2 = bLb + ((brow + ni * 8) * 40 + k16 + bcolb) * 2;
                asm volatile("ldmatrix.sync.aligned.m8n8.x2.shared.b16 {%0,%1}, [%2];"
                             : "=r"(bl[ni][0]), "=r"(bl[ni][1]) : "r"(bd2));
            }
#pragma unroll
            for (int mi = 0; mi < 4; ++mi)
#pragma unroll
                for (int ni = 0; ni < 4; ++ni)
                    MMA_OP(acc[mi][ni], ah[mi], bh[ni]);
#pragma unroll
            for (int mi = 0; mi < 4; ++mi)
#pragma unroll
                for (int ni = 0; ni < 4; ++ni)
                    MMA_OP(acc[mi][ni], ah[mi], bl[ni]);
#pragma unroll
            for (int mi = 0; mi < 4; ++mi)
#pragma unroll
                for (int ni = 0; ni < 4; ++ni)
                    MMA_OP(acc[mi][ni], al[mi], bh[ni]);
        }
        __syncthreads();
    }

    const int crow = m0 + wm * 64 + (lane >> 2);
    const int ccol = n0 + wn * 32 + (lane & 3) * 2;
    if (Ch) {
#pragma unroll
        for (int mi = 0; mi < 4; ++mi)
#pragma unroll
            for (int ni = 0; ni < 4; ++ni) {
                size_t r0 = (size_t)(crow + mi * 16) * DD + ccol + ni * 8;
                size_t r1 = (size_t)(crow + mi * 16 + 8) * DD + ccol + ni * 8;
#pragma unroll
                for (int half = 0; half < 2; ++half) {
                    float v0 = acc[mi][ni][half * 2], v1 = acc[mi][ni][half * 2 + 1];
                    __nv_bfloat16 h0 = __float2bfloat16(v0), h1 = __float2bfloat16(v1);
                    __nv_bfloat16 q0b = __float2bfloat16(v0 - __bfloat162float(h0));
                    __nv_bfloat16 q1b = __float2bfloat16(v1 - __bfloat162float(h1));
                    size_t r = half ? r1 : r0;
                    *(uint32_t*)&Ch[r] = pack2(h0, h1);
                    *(uint32_t*)&Cl[r] = pack2(q0b, q1b);
                }
            }
    } else {
#pragma unroll
        for (int mi = 0; mi < 4; ++mi)
#pragma unroll
            for (int ni = 0; ni < 4; ++ni) {
                size_t r0 = (size_t)(crow + mi * 16) * DD + ccol + ni * 8;
                size_t r1 = (size_t)(crow + mi * 16 + 8) * DD + ccol + ni * 8;
                *(float2*)&C[r0] = make_float2(acc[mi][ni][0], acc[mi][ni][1]);
                *(float2*)&C[r1] = make_float2(acc[mi][ni][2], acc[mi][ni][3]);
            }
    }
}

__global__ __launch_bounds__(256, 2)
void gemm_mma(const __nv_bfloat16* __restrict__ Ah, const __nv_bfloat16* __restrict__ Al,
              const __nv_bfloat16* __restrict__ Bh, const __nv_bfloat16* __restrict__ Bl,
              float* __restrict__ C,
              __nv_bfloat16* __restrict__ Ch, __nv_bfloat16* __restrict__ Cl) {
    extern __shared__ __align__(128) char sm[];
    gemm_body(sm, smem_u32(sm), Ah, Al, Bh, Bl,
              blockIdx.y * 128, blockIdx.x * 128, C, Ch, Cl);
}

__global__ __launch_bounds__(256, 2)
void gemm_qkv(const __nv_bfloat16* __restrict__ Ah, const __nv_bfloat16* __restrict__ Al,
              const __nv_bfloat16* __restrict__ Bh0, const __nv_bfloat16* __restrict__ Bl0,
              const __nv_bfloat16* __restrict__ Bh1, const __nv_bfloat16* __restrict__ Bl1,
              const __nv_bfloat16* __restrict__ Bh2, const __nv_bfloat16* __restrict__ Bl2,
              __nv_bfloat16* __restrict__ Ch0, __nv_bfloat16* __restrict__ Cl0,
              __nv_bfloat16* __restrict__ Ch1, __nv_bfloat16* __restrict__ Cl1,
              __nv_bfloat16* __restrict__ Ch2, __nv_bfloat16* __restrict__ Cl2) {
    extern __shared__ __align__(128) char sm[];
    int sel = blockIdx.x >> 3;
    int n0 = (blockIdx.x & 7) * 128;
    const __nv_bfloat16* Bh = (sel == 0) ? Bh0 : (sel == 1) ? Bh1 : Bh2;
    const __nv_bfloat16* Bl = (sel == 0) ? Bl0 : (sel == 1) ? Bl1 : Bl2;
    __nv_bfloat16* Ch = (sel == 0) ? Ch0 : (sel == 1) ? Ch1 : Ch2;
    __nv_bfloat16* Cl = (sel == 0) ? Cl0 : (sel == 1) ? Cl1 : Cl2;
    gemm_body(sm, smem_u32(sm), Ah, Al, Bh, Bl,
              blockIdx.y * 128, n0, nullptr, Ch, Cl);
}

// ---------------------------------------------------------------------------
// Fused flash attention. R14: Pd hi-only (lo product folded into error budget),
// Pd complement slots zeroed ONCE (k0-invariant band), -48 STS/thread/iter.
// ---------------------------------------------------------------------------
#define AQH   0
#define AQL   9216
#define AKH   18432
#define AKL   27648
#define AVH   36864
#define AVL   46080
#define AEKH  55296
#define AEKL  73728
#define AEVH  92160
#define AEVL  110592
#define AU    129024
#define APH   162816
#define APL   172032
#define ASBUF 162816          // S fp32 64x68 overlays APH/APL
#define APDH  181248          // sheared P hi, 64 x 272B
#define ASTAT 198656
#define ATTN_SMEM (198656 + 768)

__global__ __launch_bounds__(256)
void attn_fused(const __nv_bfloat16* __restrict__ Qh, const __nv_bfloat16* __restrict__ Ql,
                const __nv_bfloat16* __restrict__ Kh, const __nv_bfloat16* __restrict__ Kl,
                const __nv_bfloat16* __restrict__ Vh, const __nv_bfloat16* __restrict__ Vl,
                const __nv_bfloat16* __restrict__ Ekh, const __nv_bfloat16* __restrict__ Ekl,
                const __nv_bfloat16* __restrict__ Evh, const __nv_bfloat16* __restrict__ Evl,
                __nv_bfloat16* __restrict__ Oh, __nv_bfloat16* __restrict__ Ol) {
    extern __shared__ __align__(128) char sm[];
    const uint32_t smb = smem_u32(sm);
    const int qt = 15 - blockIdx.x;
    const int q0 = qt * 64;
    const int bh = blockIdx.y;
    const int b = bh >> 4, h = bh & 15;
    const int tid = threadIdx.x;
    const int wid = tid >> 5, lane = tid & 31;
    const int wq = wid & 3, wn = wid >> 2;
    const int frow = lane & 15;
    const int fcolb = (lane >> 4) << 3;
    const int crow = wq * 16 + (lane >> 2);
    const int ccol = (lane & 3) * 2;
    const int srow = tid >> 2, spart = tid & 3;

    float* mS = (float*)(sm + ASTAT);
    float* lS = mS + 64;
    float* fS = mS + 128;
    float* Us = (float*)(sm + AU);
    float* Sb = (float*)(sm + ASBUF);

    if (tid < 64) { mS[tid] = -1e30f; lS[tid] = 0.f; }
    // zero the full Pd buffer ONCE (valid band overwritten each iter;
    // complement slots stay zero for all iterations)
    {
        uint4 z = make_uint4(0, 0, 0, 0);
        for (int i = tid; i < 64 * 17; i += 256) {
            int r = i / 17, c = i % 17;
            *(uint4*)(sm + APDH + r * 272 + c * 16) = z;
        }
    }

    // stage Q (once)
    {
        const __nv_bfloat16* gq = Qh + (size_t)(b * LL + q0) * DD + h * HD;
        const __nv_bfloat16* gql = Ql + (size_t)(b * LL + q0) * DD + h * HD;
#pragma unroll
        for (int t = 0; t < 4; ++t) {
            int i = tid + t * 256;
            int tt = i >> 9;
            int r = (i >> 3) & 63;
            int c = i & 7;
            const __nv_bfloat16* sp = (tt ? gql : gq) + (size_t)r * DD + c * 8;
            CP16(smb + (tt ? AQL : AQH) + r * 144 + c * 16, sp);
        }
    }

    float acc[4][4];
#pragma unroll
    for (int i = 0; i < 4; ++i)
#pragma unroll
        for (int j = 0; j < 4; ++j) acc[i][j] = 0.f;

    for (int k0 = 0; k0 <= q0; k0 += 64) {
        const int base = k0 - q0 + 961;
        const bool first = (k0 == 0);
        __syncthreads();
        {
            const __nv_bfloat16* g0 = Kh + (size_t)(b * LL + k0) * DD + h * HD;
            const __nv_bfloat16* g1 = Kl + (size_t)(b * LL + k0) * DD + h * HD;
            const __nv_bfloat16* g2 = Vh + (size_t)(b * LL + k0) * DD + h * HD;
            const __nv_bfloat16* g3 = Vl + (size_t)(b * LL + k0) * DD + h * HD;
#pragma unroll
            for (int t = 0; t < 8; ++t) {
                int i = tid + t * 256;
                int tile = i >> 9;
                int r = (i >> 3) & 63;
                int c = i & 7;
                const __nv_bfloat16* sp =
                    ((tile == 0) ? g0 : (tile == 1) ? g1 : (tile == 2) ? g2 : g3)
                    + (size_t)r * DD + c * 8;
                uint32_t off = (tile == 0) ? AKH : (tile == 1) ? AKL : (tile == 2) ? AVH : AVL;
                CP16(smb + off + r * 144 + c * 16, sp);
            }
        }
        {
            int g0r = base + (first ? 0 : 64);
            int nt = first ? 16 : 8;
            int rsh = first ? 10 : 9;
            int rmask = first ? 127 : 63;
            for (int t = 0; t < nt; ++t) {
                int i = tid + t * 256;
                int tile = i >> rsh;
                int rr = (i >> 3) & rmask;
                int c = i & 7;
                int g = g0r + rr;
                const __nv_bfloat16* sp =
                    ((tile == 0) ? Ekh : (tile == 1) ? Ekl : (tile == 2) ? Evh : Evl)
                    + (size_t)g * HD + c * 8;
                uint32_t off = (tile == 0) ? AEKH : (tile == 1) ? AEKL
                             : (tile == 2) ? AEVH : AEVL;
                CP16(smb + off + (uint32_t)(g & 127) * 144 + c * 16, sp);
            }
        }
        CPWAIT();
        __syncthreads();

        // ---- S = Q·K^T and new U columns = Q·Ek^T ----
        {
            float aqk[4][4], au[8][4];
#pragma unroll
            for (int i = 0; i < 4; ++i)
#pragma unroll
                for (int j = 0; j < 4; ++j) aqk[i][j] = 0.f;
#pragma unroll
            for (int i = 0; i < 8; ++i)
#pragma unroll
                for (int j = 0; j < 4; ++j) au[i][j] = 0.f;

#pragma unroll
            for (int d16 = 0; d16 < 64; d16 += 16) {
                uint32_t ah[4], al[4];
                LDSM4(ah[0], ah[1], ah[2], ah[3],
                      smb + AQH + (wq * 16 + frow) * 144 + (d16 + fcolb) * 2);
                LDSM4(al[0], al[1], al[2], al[3],
                      smb + AQL + (wq * 16 + frow) * 144 + (d16 + fcolb) * 2);
#pragma unroll
                for (int ngl = 0; ngl < 2; ++ngl) {
                    int ng = wn * 2 + ngl;
                    uint32_t kh4[4], kl4[4];
                    LDSM4(kh4[0], kh4[1], kh4[2], kh4[3],
                          smb + AKH + (ng * 16 + frow) * 144 + (d16 + fcolb) * 2);
                    LDSM4(kl4[0], kl4[1], kl4[2], kl4[3],
                          smb + AKL + (ng * 16 + frow) * 144 + (d16 + fcolb) * 2);
                    uint32_t f0h[2] = {kh4[0], kh4[2]}, f1h[2] = {kh4[1], kh4[3]};
                    uint32_t f0l[2] = {kl4[0], kl4[2]}, f1l[2] = {kl4[1], kl4[3]};
                    MMA_OP(aqk[2 * ngl],     ah, f0h);
                    MMA_OP(aqk[2 * ngl],     ah, f0l);
                    MMA_OP(aqk[2 * ngl],     al, f0h);
                    MMA_OP(aqk[2 * ngl + 1], ah, f1h);
                    MMA_OP(aqk[2 * ngl + 1], ah, f1l);
                    MMA_OP(aqk[2 * ngl + 1], al, f1h);
                }
                if (first) {
#pragma unroll
                    for (int ngl = 0; ngl < 4; ++ngl) {
                        int lr = (wn * 4 + ngl) * 16;
                        uint32_t e4h[4], e4l[4];
                        uint32_t ra = (uint32_t)((base + lr + frow) & 127) * 144 + (d16 + fcolb) * 2;
                        LDSM4(e4h[0], e4h[1], e4h[2], e4h[3], smb + AEKH + ra);
                        LDSM4(e4l[0], e4l[1], e4l[2], e4l[3], smb + AEKL + ra);
                        uint32_t f0h[2] = {e4h[0], e4h[2]}, f1h[2] = {e4h[1], e4h[3]};
                        uint32_t f0l[2] = {e4l[0], e4l[2]}, f1l[2] = {e4l[1], e4l[3]};
                        MMA_OP(au[2 * ngl],     ah, f0h);
                        MMA_OP(au[2 * ngl],     ah, f0l);
                        MMA_OP(au[2 * ngl],     al, f0h);
                        MMA_OP(au[2 * ngl + 1], ah, f1h);
                        MMA_OP(au[2 * ngl + 1], ah, f1l);
                        MMA_OP(au[2 * ngl + 1], al, f1h);
                    }
                } else {
#pragma unroll
                    for (int ngl = 0; ngl < 2; ++ngl) {
                        int lr = 64 + (wn * 2 + ngl) * 16;
                        uint32_t e4h[4], e4l[4];
                        uint32_t ra = (uint32_t)((base + lr + frow) & 127) * 144 + (d16 + fcolb) * 2;
                        LDSM4(e4h[0], e4h[1], e4h[2], e4h[3], smb + AEKH + ra);
                        LDSM4(e4l[0], e4l[1], e4l[2], e4l[3], smb + AEKL + ra);
                        uint32_t f0h[2] = {e4h[0], e4h[2]}, f1h[2] = {e4h[1], e4h[3]};
                        uint32_t f0l[2] = {e4l[0], e4l[2]}, f1l[2] = {e4l[1], e4l[3]};
                        MMA_OP(au[2 * ngl],     ah, f0h);
                        MMA_OP(au[2 * ngl],     ah, f0l);
                        MMA_OP(au[2 * ngl],     al, f0h);
                        MMA_OP(au[2 * ngl + 1], ah, f1h);
                        MMA_OP(au[2 * ngl + 1], ah, f1l);
                        MMA_OP(au[2 * ngl + 1], al, f1h);
                    }
                }
            }
#pragma unroll
            for (int ia = 0; ia < 4; ++ia) {
                int kcol = (wn * 2 + (ia >> 1)) * 16 + (ia & 1) * 8 + ccol;
                Sb[crow * 68 + kcol]           = aqk[ia][0];
                Sb[crow * 68 + kcol + 1]       = aqk[ia][1];
                Sb[(crow + 8) * 68 + kcol]     = aqk[ia][2];
                Sb[(crow + 8) * 68 + kcol + 1] = aqk[ia][3];
            }
            int cnt = first ? 8 : 4;
            for (int ia = 0; ia < cnt; ++ia) {
                int lr = (first ? (wn * 4 + (ia >> 1)) * 16
                                : 64 + (wn * 2 + (ia >> 1)) * 16) + (ia & 1) * 8 + ccol;
                int p0 = (base + lr) & 127;
                int p1 = (base + lr + 1) & 127;
                Us[crow * 132 + p0]       = au[ia][0];
                Us[crow * 132 + p1]       = au[ia][1];
                Us[(crow + 8) * 132 + p0] = au[ia][2];
                Us[(crow + 8) * 132 + p1] = au[ia][3];
            }
        }
        __syncthreads();

        // ---- online softmax ----
        float p[16];
        {
            int qg = q0 + srow;
            float mx = -1e30f;
#pragma unroll
            for (int j = 0; j < 16; ++j) {
                int c = spart * 16 + j;
                int pc = (base + c - srow + 63) & 127;
                float s = (Sb[srow * 68 + c] + Us[srow * 132 + pc]) * 0.125f;
                if (k0 + c > qg) s = -1e30f;
                p[j] = s;
                mx = fmaxf(mx, s);
            }
            mx = fmaxf(mx, __shfl_xor_sync(0xffffffffu, mx, 1));
            mx = fmaxf(mx, __shfl_xor_sync(0xffffffffu, mx, 2));
            float mold = mS[srow];
            float mnew = fmaxf(mold, mx);
            float fct = __expf(mold - mnew);
            float rs = 0.f;
#pragma unroll
            for (int j = 0; j < 16; ++j) { p[j] = __expf(p[j] - mnew); rs += p[j]; }
            rs += __shfl_xor_sync(0xffffffffu, rs, 1);
            rs += __shfl_xor_sync(0xffffffffu, rs, 2);
            if (spart == 0) {
                mS[srow] = mnew;
                lS[srow] = lS[srow] * fct + rs;
                fS[srow] = fct;
            }
        }
        __syncthreads();

        // ---- stage P (hi/lo) and sheared Pd (hi only; complements pre-zeroed) ----
#pragma unroll
        for (int j2 = 0; j2 < 8; ++j2) {
            int c = spart * 16 + j2 * 2;
            float v0 = p[j2 * 2], v1 = p[j2 * 2 + 1];
            __nv_bfloat16 h0 = __float2bfloat16(v0), h1 = __float2bfloat16(v1);
            __nv_bfloat16 l0 = __float2bfloat16(v0 - __bfloat162float(h0));
            __nv_bfloat16 l1 = __float2bfloat16(v1 - __bfloat162float(h1));
            *(uint32_t*)(sm + APH + srow * 144 + c * 2) = pack2(h0, h1);
            *(uint32_t*)(sm + APL + srow * 144 + c * 2) = pack2(l0, l1);
            int r = c - srow + 63;
            *(uint16_t*)(sm + APDH + srow * 272 + r * 2) = bf16bits(h0);
            *(uint16_t*)(sm + APDH + srow * 272 + (r + 1) * 2) = bf16bits(h1);
        }
        {
            float f0 = fS[crow], f1 = fS[crow + 8];
#pragma unroll
            for (int ni = 0; ni < 4; ++ni) {
                acc[ni][0] *= f0; acc[ni][1] *= f0;
                acc[ni][2] *= f1; acc[ni][3] *= f1;
            }
        }
        __syncthreads();

        // ---- O += P·V (full hi/lo) ----
#pragma unroll
        for (int k16 = 0; k16 < 64; k16 += 16) {
            uint32_t ph[4], pl[4];
            LDSM4(ph[0], ph[1], ph[2], ph[3],
                  smb + APH + (wq * 16 + frow) * 144 + (k16 + fcolb) * 2);
            LDSM4(pl[0], pl[1], pl[2], pl[3],
                  smb + APL + (wq * 16 + frow) * 144 + (k16 + fcolb) * 2);
#pragma unroll
            for (int ngl = 0; ngl < 2; ++ngl) {
                int ng = wn * 2 + ngl;
                uint32_t vh4[4], vl4[4];
                LDSM4T(vh4[0], vh4[1], vh4[2], vh4[3],
                       smb + AVH + (k16 + frow) * 144 + (ng * 16 + fcolb) * 2);
                LDSM4T(vl4[0], vl4[1], vl4[2], vl4[3],
                       smb + AVL + (k16 + frow) * 144 + (ng * 16 + fcolb) * 2);
                uint32_t f0h[2] = {vh4[0], vh4[1]}, f1h[2] = {vh4[2], vh4[3]};
                uint32_t f0l[2] = {vl4[0], vl4[1]}, f1l[2] = {vl4[2], vl4[3]};
                MMA_OP(acc[2 * ngl],     ph, f0h);
                MMA_OP(acc[2 * ngl],     ph, f0l);
                MMA_OP(acc[2 * ngl],     pl, f0h);
                MMA_OP(acc[2 * ngl + 1], ph, f1h);
                MMA_OP(acc[2 * ngl + 1], ph, f1l);
                MMA_OP(acc[2 * ngl + 1], pl, f1h);
            }
        }
        // ---- O += Pd·Ev (banded; Pd hi only, Ev hi+lo) ----
        {
            const int rs0 = 48 - wq * 16;
#pragma unroll
            for (int k5 = 0; k5 < 5; ++k5) {
                int r16 = rs0 + k5 * 16;
                uint32_t ph[4];
                LDSM4(ph[0], ph[1], ph[2], ph[3],
                      smb + APDH + (wq * 16 + frow) * 272 + (r16 + fcolb) * 2);
#pragma unroll
                for (int ngl = 0; ngl < 2; ++ngl) {
                    int ng = wn * 2 + ngl;
                    uint32_t eh4[4], el4[4];
                    uint32_t ra = (uint32_t)((base + r16 + frow) & 127) * 144 + (ng * 16 + fcolb) * 2;
                    LDSM4T(eh4[0], eh4[1], eh4[2], eh4[3], smb + AEVH + ra);
                    LDSM4T(el4[0], el4[1], el4[2], el4[3], smb + AEVL + ra);
                    uint32_t f0h[2] = {eh4[0], eh4[1]}, f1h[2] = {eh4[2], eh4[3]};
                    uint32_t f0l[2] = {el4[0], el4[1]}, f1l[2] = {el4[2], el4[3]};
                    MMA_OP(acc[2 * ngl],     ph, f0h);
                    MMA_OP(acc[2 * ngl],     ph, f0l);
                    MMA_OP(acc[2 * ngl + 1], ph, f1h);
                    MMA_OP(acc[2 * ngl + 1], ph, f1l);
                }
            }
        }
    }

    float inv0 = 1.f / lS[crow];
    float inv1 = 1.f / lS[crow + 8];
    __nv_bfloat16* Ogh = Oh + (size_t)(b * LL + q0) * DD + h * HD;
    __nv_bfloat16* Ogl = Ol + (size_t)(b * LL + q0) * DD + h * HD;
#pragma unroll
    for (int ia = 0; ia < 4; ++ia) {
        int col = wn * 32 + (ia >> 1) * 16 + (ia & 1) * 8 + ccol;
#pragma unroll
        for (int hf = 0; hf < 2; ++hf) {
            float v0 = acc[ia][hf * 2]     * (hf ? inv1 : inv0);
            float v1 = acc[ia][hf * 2 + 1] * (hf ? inv1 : inv0);
            __nv_bfloat16 h0 = __float2bfloat16(v0), h1 = __float2bfloat16(v1);
            __nv_bfloat16 l0 = __float2bfloat16(v0 - __bfloat162float(h0));
            __nv_bfloat16 l1 = __float2bfloat16(v1 - __bfloat162float(h1));
            size_t off = (size_t)(crow + hf * 8) * DD + col;
            *(uint32_t*)&Ogh[off] = pack2(h0, h1);
            *(uint32_t*)&Ogl[off] = pack2(l0, l1);
        }
    }
}

// ---------------------------------------------------------------------------
// Launch
// ---------------------------------------------------------------------------
extern "C" void kernel_launch(void* const* d_in, const int* in_sizes, int n_in,
                              void* d_out, int out_size) {
    const float* x   = (const float*)d_in[0];
    const float* Wq  = (const float*)d_in[1];
    const float* Wk  = (const float*)d_in[2];
    const float* Wv  = (const float*)d_in[3];
    const float* Wo  = (const float*)d_in[4];
    const float* pek = (const float*)d_in[5];
    const float* pev = (const float*)d_in[6];
    float* out = (float*)d_out;

    __nv_bfloat16 *xh, *xl, *wh, *wl, *wqh, *wql, *wkh, *wkl, *wvh, *wvl;
    __nv_bfloat16 *Qh, *Ql, *Kh, *Kl, *Vh, *Vl, *Oh, *Ol;
    __nv_bfloat16 *pekh, *pekl, *pevh, *pevl;
    cudaGetSymbolAddress((void**)&xh, g_xh);
    cudaGetSymbolAddress((void**)&xl, g_xl);
    cudaGetSymbolAddress((void**)&wh, g_wh);
    cudaGetSymbolAddress((void**)&wl, g_wl);
    cudaGetSymbolAddress((void**)&wqh, g_wqh);
    cudaGetSymbolAddress((void**)&wql, g_wql);
    cudaGetSymbolAddress((void**)&wkh, g_wkh);
    cudaGetSymbolAddress((void**)&wkl, g_wkl);
    cudaGetSymbolAddress((void**)&wvh, g_wvh);
    cudaGetSymbolAddress((void**)&wvl, g_wvl);
    cudaGetSymbolAddress((void**)&Qh, g_Qh);
    cudaGetSymbolAddress((void**)&Ql, g_Ql);
    cudaGetSymbolAddress((void**)&Kh, g_Kh);
    cudaGetSymbolAddress((void**)&Kl, g_Kl);
    cudaGetSymbolAddress((void**)&Vh, g_Vh);
    cudaGetSymbolAddress((void**)&Vl, g_Vl);
    cudaGetSymbolAddress((void**)&Oh, g_Oh);
    cudaGetSymbolAddress((void**)&Ol, g_Ol);
    cudaGetSymbolAddress((void**)&pekh, g_pekh);
    cudaGetSymbolAddress((void**)&pekl, g_pekl);
    cudaGetSymbolAddress((void**)&pevh, g_pevh);
    cudaGetSymbolAddress((void**)&pevl, g_pevl);

    cudaFuncSetAttribute(gemm_mma, cudaFuncAttributeMaxDynamicSharedMemorySize, GEMM_SMEM);
    cudaFuncSetAttribute(gemm_qkv, cudaFuncAttributeMaxDynamicSharedMemorySize, GEMM_SMEM);
    cudaFuncSetAttribute(attn_fused, cudaFuncAttributeMaxDynamicSharedMemorySize, ATTN_SMEM);

    const int n4w = DD * DD / 4;
    dim3 ggemm(DD / 128, MROWS / 128);
    dim3 gqkv(3 * DD / 128, MROWS / 128);

    split6_kernel<<<7426, 256>>>(x, Wq, Wk, Wv, pek, pev,
                                 xh, xl, wqh, wql, wkh, wkl, wvh, wvl,
                                 pekh, pekl, pevh, pevl);
    gemm_qkv<<<gqkv, 256, GEMM_SMEM>>>(xh, xl, wqh, wql, wkh, wkl, wvh, wvl,
                                       Qh, Ql, Kh, Kl, Vh, Vl);
    split_kernel<<<(n4w + 255) / 256, 256>>>(Wo, wh, wl, n4w);
    attn_fused<<<dim3(16, 64), 256, ATTN_SMEM>>>(Qh, Ql, Kh, Kl, Vh, Vl,
                                                 pekh, pekl, pevh, pevl, Oh, Ol);
    gemm_mma<<<ggemm, 256, GEMM_SMEM>>>(Oh, Ol, wh, wl, out, nullptr, nullptr);
}

// round 15
// speedup vs baseline: 1.2297x; 1.0655x over previous
#include <cuda_runtime.h>
#include <cuda_bf16.h>
#include <cstdint>

// Problem constants
#define BB 4
#define LL 1024
#define DD 1024
#define HH 16
#define HD 64
#define MROWS 4096           // B*L
#define PEN 2049

// Scratch (device globals; allocation is forbidden)
__device__ __nv_bfloat16 g_xh[MROWS * DD];
__device__ __nv_bfloat16 g_xl[MROWS * DD];
__device__ __nv_bfloat16 g_wqh[DD * DD];
__device__ __nv_bfloat16 g_wql[DD * DD];
__device__ __nv_bfloat16 g_wkh[DD * DD];
__device__ __nv_bfloat16 g_wkl[DD * DD];
__device__ __nv_bfloat16 g_wvh[DD * DD];
__device__ __nv_bfloat16 g_wvl[DD * DD];
__device__ __nv_bfloat16 g_wh[DD * DD];
__device__ __nv_bfloat16 g_wl[DD * DD];
__device__ __nv_bfloat16 g_Qh[MROWS * DD];
__device__ __nv_bfloat16 g_Ql[MROWS * DD];
__device__ __nv_bfloat16 g_Kh[MROWS * DD];
__device__ __nv_bfloat16 g_Kl[MROWS * DD];
__device__ __nv_bfloat16 g_Vh[MROWS * DD];
__device__ __nv_bfloat16 g_Vl[MROWS * DD];
__device__ __nv_bfloat16 g_Oh[MROWS * DD];
__device__ __nv_bfloat16 g_Ol[MROWS * DD];
__device__ __nv_bfloat16 g_pekh[PEN * HD];
__device__ __nv_bfloat16 g_pekl[PEN * HD];
__device__ __nv_bfloat16 g_pevh[PEN * HD];
__device__ __nv_bfloat16 g_pevl[PEN * HD];

__device__ __forceinline__ uint32_t smem_u32(const void* p) {
    uint32_t a;
    asm("{ .reg .u64 t; cvta.to.shared.u64 t, %1; cvt.u32.u64 %0, t; }" : "=r"(a) : "l"(p));
    return a;
}

#define MMA_OP(c, af, bf) \
    asm volatile("mma.sync.aligned.m16n8k16.row.col.f32.bf16.bf16.f32 " \
                 "{%0,%1,%2,%3}, {%4,%5,%6,%7}, {%8,%9}, {%0,%1,%2,%3};" \
                 : "+f"((c)[0]), "+f"((c)[1]), "+f"((c)[2]), "+f"((c)[3]) \
                 : "r"((af)[0]), "r"((af)[1]), "r"((af)[2]), "r"((af)[3]), \
                   "r"((bf)[0]), "r"((bf)[1]))

#define LDSM4(d0,d1,d2,d3,a) \
    asm volatile("ldmatrix.sync.aligned.m8n8.x4.shared.b16 {%0,%1,%2,%3}, [%4];" \
                 : "=r"(d0), "=r"(d1), "=r"(d2), "=r"(d3) : "r"(a))
#define LDSM4T(d0,d1,d2,d3,a) \
    asm volatile("ldmatrix.sync.aligned.m8n8.x4.trans.shared.b16 {%0,%1,%2,%3}, [%4];" \
                 : "=r"(d0), "=r"(d1), "=r"(d2), "=r"(d3) : "r"(a))

#define CP16(dst, src) \
    asm volatile("cp.async.cg.shared.global [%0], [%1], 16;" :: "r"(dst), "l"(src))
#define CPWAIT() \
    asm volatile("cp.async.commit_group;\n\tcp.async.wait_group 0;" ::: "memory")

__device__ __forceinline__ uint32_t pack2(__nv_bfloat16 a, __nv_bfloat16 b) {
    __nv_bfloat162 t(a, b);
    return *reinterpret_cast<uint32_t*>(&t);
}
__device__ __forceinline__ uint16_t bf16bits(__nv_bfloat16 h) {
    return *reinterpret_cast<uint16_t*>(&h);
}

// ---------------------------------------------------------------------------
// fp32 -> bf16 hi/lo split
// ---------------------------------------------------------------------------
__device__ __forceinline__ void split4(const float* s, __nv_bfloat16* h,
                                       __nv_bfloat16* l, int i) {
    float4 v = ((const float4*)s)[i];
    __nv_bfloat16 h0 = __float2bfloat16(v.x);
    __nv_bfloat16 h1 = __float2bfloat16(v.y);
    __nv_bfloat16 h2 = __float2bfloat16(v.z);
    __nv_bfloat16 h3 = __float2bfloat16(v.w);
    __nv_bfloat16 l0 = __float2bfloat16(v.x - __bfloat162float(h0));
    __nv_bfloat16 l1 = __float2bfloat16(v.y - __bfloat162float(h1));
    __nv_bfloat16 l2 = __float2bfloat16(v.z - __bfloat162float(h2));
    __nv_bfloat16 l3 = __float2bfloat16(v.w - __bfloat162float(h3));
    ((uint2*)h)[i] = make_uint2(pack2(h0, h1), pack2(h2, h3));
    ((uint2*)l)[i] = make_uint2(pack2(l0, l1), pack2(l2, l3));
}

__global__ __launch_bounds__(256)
void split_kernel(const float* __restrict__ s, __nv_bfloat16* __restrict__ h,
                  __nv_bfloat16* __restrict__ l, int n4) {
    int i = blockIdx.x * 256 + threadIdx.x;
    if (i >= n4) return;
    split4(s, h, l, i);
}

__global__ __launch_bounds__(256)
void split6_kernel(const float* __restrict__ x, const float* __restrict__ Wq,
                   const float* __restrict__ Wk, const float* __restrict__ Wv,
                   const float* __restrict__ pek, const float* __restrict__ pev,
                   __nv_bfloat16* __restrict__ xh, __nv_bfloat16* __restrict__ xl,
                   __nv_bfloat16* __restrict__ wqh, __nv_bfloat16* __restrict__ wql,
                   __nv_bfloat16* __restrict__ wkh, __nv_bfloat16* __restrict__ wkl,
                   __nv_bfloat16* __restrict__ wvh, __nv_bfloat16* __restrict__ wvl,
                   __nv_bfloat16* __restrict__ pkh, __nv_bfloat16* __restrict__ pkl,
                   __nv_bfloat16* __restrict__ pvh, __nv_bfloat16* __restrict__ pvl) {
    int blk = blockIdx.x;
    const float* s; __nv_bfloat16 *h, *l; int i, n4;
    if (blk < 4096)      { s = x;   h = xh;  l = xl;  i = blk * 256 + threadIdx.x; n4 = 1048576; }
    else if (blk < 5120) { s = Wq;  h = wqh; l = wql; i = (blk - 4096) * 256 + threadIdx.x; n4 = 262144; }
    else if (blk < 6144) { s = Wk;  h = wkh; l = wkl; i = (blk - 5120) * 256 + threadIdx.x; n4 = 262144; }
    else if (blk < 7168) { s = Wv;  h = wvh; l = wvl; i = (blk - 6144) * 256 + threadIdx.x; n4 = 262144; }
    else if (blk < 7297) { s = pek; h = pkh; l = pkl; i = (blk - 7168) * 256 + threadIdx.x; n4 = 32784; }
    else                 { s = pev; h = pvh; l = pvl; i = (blk - 7297) * 256 + threadIdx.x; n4 = 32784; }
    if (i >= n4) return;
    split4(s, h, l, i);
}

// ---------------------------------------------------------------------------
// GEMM core: 256 threads, warp grid 2(m) x 4(n), tile 64x32, 2 CTAs/SM.
// ---------------------------------------------------------------------------
#define GKDIM 1024
#define NIT 32
#define TILE_B 10240
#define STAGE_B (4 * TILE_B)
#define GEMM_SMEM (2 * STAGE_B)

__device__ __forceinline__
void gemm_body(char* sm, uint32_t smb,
               const __nv_bfloat16* Ah, const __nv_bfloat16* Al,
               const __nv_bfloat16* Bh, const __nv_bfloat16* Bl,
               int m0, int n0,
               float* C, __nv_bfloat16* Ch, __nv_bfloat16* Cl) {
    const int tid = threadIdx.x;
    const int wid = tid >> 5, lane = tid & 31;
    const int wm = wid & 1, wn = wid >> 1;

    const __nv_bfloat16* srcs[4] = {
        Ah + (size_t)m0 * GKDIM, Al + (size_t)m0 * GKDIM,
        Bh + (size_t)n0 * GKDIM, Bl + (size_t)n0 * GKDIM };

    auto stage_load = [&](int kc, int s) {
#pragma unroll
        for (int rep = 0; rep < 8; ++rep) {
            int idx = tid + rep * 256;
            int tile = idx >> 9;
            int r = (idx >> 2) & 127;
            int c = idx & 3;
            const void* gp = srcs[tile] + (size_t)r * GKDIM + kc * 32 + c * 8;
            uint32_t dp = smb + s * STAGE_B + tile * TILE_B + r * 80 + c * 16;
            CP16(dp, gp);
        }
        asm volatile("cp.async.commit_group;");
    };

    float acc[4][4][4];
#pragma unroll
    for (int i = 0; i < 4; ++i)
#pragma unroll
        for (int j = 0; j < 4; ++j)
#pragma unroll
            for (int k = 0; k < 4; ++k) acc[i][j][k] = 0.f;

    stage_load(0, 0);

    for (int it = 0; it < NIT; ++it) {
        if (it + 1 < NIT) {
            stage_load(it + 1, (it + 1) & 1);
            asm volatile("cp.async.wait_group 1;");
        } else {
            asm volatile("cp.async.wait_group 0;");
        }
        __syncthreads();

        const uint32_t base = smb + (it & 1) * STAGE_B;
        const uint32_t aHb = base, aLb = base + TILE_B;
        const uint32_t bHb = base + 2 * TILE_B, bLb = base + 3 * TILE_B;
        const int arow = wm * 64 + (lane & 15);
        const int acolb = (lane & 16) >> 1;
        const int brow = wn * 32 + (lane & 7);
        const int bcolb = lane & 8;

#pragma unroll
        for (int k16 = 0; k16 < 32; k16 += 16) {
            uint32_t ah[4][4], al[4][4], bh[4][2], bl[4][2];
#pragma unroll
            for (int mi = 0; mi < 4; ++mi) {
                uint32_t ad = aHb + ((arow + mi * 16) * 40 + k16 + acolb) * 2;
                LDSM4(ah[mi][0], ah[mi][1], ah[mi][2], ah[mi][3], ad);
                uint32_t ad2 = aLb + ((arow + mi * 16) * 40 + k16 + acolb) * 2;
                LDSM4(al[mi][0], al[mi][1], al[mi][2], al[mi][3], ad2);
            }
#pragma unroll
            for (int ni = 0; ni < 4; ++ni) {
                uint32_t bd = bHb + ((brow + ni * 8) * 40 + k16 + bcolb) * 2;
                asm volatile("ldmatrix.sync.aligned.m8n8.x2.shared.b16 {%0,%1}, [%2];"
                             : "=r"(bh[ni][0]), "=r"(bh[ni][1]) : "r"(bd));
                uint32_t bd2 = bLb + ((brow + ni * 8) * 40 + k16 + bcolb) * 2;
                asm volatile("ldmatrix.sync.aligned.m8n8.x2.shared.b16 {%0,%1}, [%2];"
                             : "=r"(bl[ni][0]), "=r"(bl[ni][1]) : "r"(bd2));
            }
#pragma unroll
            for (int mi = 0; mi < 4; ++mi)
#pragma unroll
                for (int ni = 0; ni < 4; ++ni)
                    MMA_OP(acc[mi][ni], ah[mi], bh[ni]);
#pragma unroll
            for (int mi = 0; mi < 4; ++mi)
#pragma unroll
                for (int ni = 0; ni < 4; ++ni)
                    MMA_OP(acc[mi][ni], ah[mi], bl[ni]);
#pragma unroll
            for (int mi = 0; mi < 4; ++mi)
#pragma unroll
                for (int ni = 0; ni < 4; ++ni)
                    MMA_OP(acc[mi][ni], al[mi], bh[ni]);
        }
        __syncthreads();
    }

    const int crow = m0 + wm * 64 + (lane >> 2);
    const int ccol = n0 + wn * 32 + (lane & 3) * 2;
    if (Ch) {
#pragma unroll
        for (int mi = 0; mi < 4; ++mi)
#pragma unroll
            for (int ni = 0; ni < 4; ++ni) {
                size_t r0 = (size_t)(crow + mi * 16) * DD + ccol + ni * 8;
                size_t r1 = (size_t)(crow + mi * 16 + 8) * DD + ccol + ni * 8;
#pragma unroll
                for (int half = 0; half < 2; ++half) {
                    float v0 = acc[mi][ni][half * 2], v1 = acc[mi][ni][half * 2 + 1];
                    __nv_bfloat16 h0 = __float2bfloat16(v0), h1 = __float2bfloat16(v1);
                    __nv_bfloat16 q0b = __float2bfloat16(v0 - __bfloat162float(h0));
                    __nv_bfloat16 q1b = __float2bfloat16(v1 - __bfloat162float(h1));
                    size_t r = half ? r1 : r0;
                    *(uint32_t*)&Ch[r] = pack2(h0, h1);
                    *(uint32_t*)&Cl[r] = pack2(q0b, q1b);
                }
            }
    } else {
#pragma unroll
        for (int mi = 0; mi < 4; ++mi)
#pragma unroll
            for (int ni = 0; ni < 4; ++ni) {
                size_t r0 = (size_t)(crow + mi * 16) * DD + ccol + ni * 8;
                size_t r1 = (size_t)(crow + mi * 16 + 8) * DD + ccol + ni * 8;
                *(float2*)&C[r0] = make_float2(acc[mi][ni][0], acc[mi][ni][1]);
                *(float2*)&C[r1] = make_float2(acc[mi][ni][2], acc[mi][ni][3]);
            }
    }
}

__global__ __launch_bounds__(256, 2)
void gemm_mma(const __nv_bfloat16* __restrict__ Ah, const __nv_bfloat16* __restrict__ Al,
              const __nv_bfloat16* __restrict__ Bh, const __nv_bfloat16* __restrict__ Bl,
              float* __restrict__ C,
              __nv_bfloat16* __restrict__ Ch, __nv_bfloat16* __restrict__ Cl) {
    extern __shared__ __align__(128) char sm[];
    gemm_body(sm, smem_u32(sm), Ah, Al, Bh, Bl,
              blockIdx.y * 128, blockIdx.x * 128, C, Ch, Cl);
}

__global__ __launch_bounds__(256, 2)
void gemm_qkv(const __nv_bfloat16* __restrict__ Ah, const __nv_bfloat16* __restrict__ Al,
              const __nv_bfloat16* __restrict__ Bh0, const __nv_bfloat16* __restrict__ Bl0,
              const __nv_bfloat16* __restrict__ Bh1, const __nv_bfloat16* __restrict__ Bl1,
              const __nv_bfloat16* __restrict__ Bh2, const __nv_bfloat16* __restrict__ Bl2,
              __nv_bfloat16* __restrict__ Ch0, __nv_bfloat16* __restrict__ Cl0,
              __nv_bfloat16* __restrict__ Ch1, __nv_bfloat16* __restrict__ Cl1,
              __nv_bfloat16* __restrict__ Ch2, __nv_bfloat16* __restrict__ Cl2) {
    extern __shared__ __align__(128) char sm[];
    int sel = blockIdx.x >> 3;
    int n0 = (blockIdx.x & 7) * 128;
    const __nv_bfloat16* Bh = (sel == 0) ? Bh0 : (sel == 1) ? Bh1 : Bh2;
    const __nv_bfloat16* Bl = (sel == 0) ? Bl0 : (sel == 1) ? Bl1 : Bl2;
    __nv_bfloat16* Ch = (sel == 0) ? Ch0 : (sel == 1) ? Ch1 : Ch2;
    __nv_bfloat16* Cl = (sel == 0) ? Cl0 : (sel == 1) ? Cl1 : Cl2;
    gemm_body(sm, smem_u32(sm), Ah, Al, Bh, Bl,
              blockIdx.y * 128, n0, nullptr, Ch, Cl);
}

// ---------------------------------------------------------------------------
// Fused flash attention. R15: Ek and Ev staged HI-ONLY (bias-term lo products
// folded into the error budget). U MMAs 384->256, PdEv 320->160 per iter,
// E staging halved, smem 199KB -> 162KB.
// ---------------------------------------------------------------------------
#define AQH   0
#define AQL   9216
#define AKH   18432
#define AKL   27648
#define AVH   36864
#define AVL   46080
#define AEKH  55296                  // 128 x 144B (hi only)
#define AEVH  73728                  // 128 x 144B (hi only)
#define AU    92160                  // 64 x 132 fp32
#define APH   125952
#define APL   135168
#define ASBUF 125952                 // S fp32 64x68 overlays APH/APL
#define APDH  144384                 // sheared P hi, 64 x 272B
#define ASTAT 161792
#define ATTN_SMEM (161792 + 768)

__global__ __launch_bounds__(256)
void attn_fused(const __nv_bfloat16* __restrict__ Qh, const __nv_bfloat16* __restrict__ Ql,
                const __nv_bfloat16* __restrict__ Kh, const __nv_bfloat16* __restrict__ Kl,
                const __nv_bfloat16* __restrict__ Vh, const __nv_bfloat16* __restrict__ Vl,
                const __nv_bfloat16* __restrict__ Ekh,
                const __nv_bfloat16* __restrict__ Evh,
                __nv_bfloat16* __restrict__ Oh, __nv_bfloat16* __restrict__ Ol) {
    extern __shared__ __align__(128) char sm[];
    const uint32_t smb = smem_u32(sm);
    const int qt = 15 - blockIdx.x;
    const int q0 = qt * 64;
    const int bh = blockIdx.y;
    const int b = bh >> 4, h = bh & 15;
    const int tid = threadIdx.x;
    const int wid = tid >> 5, lane = tid & 31;
    const int wq = wid & 3, wn = wid >> 2;
    const int frow = lane & 15;
    const int fcolb = (lane >> 4) << 3;
    const int crow = wq * 16 + (lane >> 2);
    const int ccol = (lane & 3) * 2;
    const int srow = tid >> 2, spart = tid & 3;

    float* mS = (float*)(sm + ASTAT);
    float* lS = mS + 64;
    float* fS = mS + 128;
    float* Us = (float*)(sm + AU);
    float* Sb = (float*)(sm + ASBUF);

    if (tid < 64) { mS[tid] = -1e30f; lS[tid] = 0.f; }
    // zero Pd once (complement slots stay zero across all iterations)
    {
        uint4 z = make_uint4(0, 0, 0, 0);
        for (int i = tid; i < 64 * 17; i += 256) {
            int r = i / 17, c = i % 17;
            *(uint4*)(sm + APDH + r * 272 + c * 16) = z;
        }
    }

    // stage Q (once)
    {
        const __nv_bfloat16* gq = Qh + (size_t)(b * LL + q0) * DD + h * HD;
        const __nv_bfloat16* gql = Ql + (size_t)(b * LL + q0) * DD + h * HD;
#pragma unroll
        for (int t = 0; t < 4; ++t) {
            int i = tid + t * 256;
            int tt = i >> 9;
            int r = (i >> 3) & 63;
            int c = i & 7;
            const __nv_bfloat16* sp = (tt ? gql : gq) + (size_t)r * DD + c * 8;
            CP16(smb + (tt ? AQL : AQH) + r * 144 + c * 16, sp);
        }
    }

    float acc[4][4];
#pragma unroll
    for (int i = 0; i < 4; ++i)
#pragma unroll
        for (int j = 0; j < 4; ++j) acc[i][j] = 0.f;

    for (int k0 = 0; k0 <= q0; k0 += 64) {
        const int base = k0 - q0 + 961;
        const bool first = (k0 == 0);
        __syncthreads();
        // stage K, V (hi/lo)
        {
            const __nv_bfloat16* g0 = Kh + (size_t)(b * LL + k0) * DD + h * HD;
            const __nv_bfloat16* g1 = Kl + (size_t)(b * LL + k0) * DD + h * HD;
            const __nv_bfloat16* g2 = Vh + (size_t)(b * LL + k0) * DD + h * HD;
            const __nv_bfloat16* g3 = Vl + (size_t)(b * LL + k0) * DD + h * HD;
#pragma unroll
            for (int t = 0; t < 8; ++t) {
                int i = tid + t * 256;
                int tile = i >> 9;
                int r = (i >> 3) & 63;
                int c = i & 7;
                const __nv_bfloat16* sp =
                    ((tile == 0) ? g0 : (tile == 1) ? g1 : (tile == 2) ? g2 : g3)
                    + (size_t)r * DD + c * 8;
                uint32_t off = (tile == 0) ? AKH : (tile == 1) ? AKL : (tile == 2) ? AVH : AVL;
                CP16(smb + off + r * 144 + c * 16, sp);
            }
        }
        // stage Ek/Ev (HI only, circular): first iter 128 rows, else 64 new
        {
            int g0r = base + (first ? 0 : 64);
            int nt = first ? 8 : 4;
            int rsh = first ? 10 : 9;
            int rmask = first ? 127 : 63;
            for (int t = 0; t < nt; ++t) {
                int i = tid + t * 256;
                int tile = i >> rsh;           // 0..1
                int rr = (i >> 3) & rmask;
                int c = i & 7;
                int g = g0r + rr;
                const __nv_bfloat16* sp = (tile ? Evh : Ekh) + (size_t)g * HD + c * 8;
                uint32_t off = tile ? AEVH : AEKH;
                CP16(smb + off + (uint32_t)(g & 127) * 144 + c * 16, sp);
            }
        }
        CPWAIT();
        __syncthreads();

        // ---- S = Q·K^T (hi/lo x3) and new U columns = Q(hi+lo)·Ekh ----
        {
            float aqk[4][4], au[8][4];
#pragma unroll
            for (int i = 0; i < 4; ++i)
#pragma unroll
                for (int j = 0; j < 4; ++j) aqk[i][j] = 0.f;
#pragma unroll
            for (int i = 0; i < 8; ++i)
#pragma unroll
                for (int j = 0; j < 4; ++j) au[i][j] = 0.f;

#pragma unroll
            for (int d16 = 0; d16 < 64; d16 += 16) {
                uint32_t ah[4], al[4];
                LDSM4(ah[0], ah[1], ah[2], ah[3],
                      smb + AQH + (wq * 16 + frow) * 144 + (d16 + fcolb) * 2);
                LDSM4(al[0], al[1], al[2], al[3],
                      smb + AQL + (wq * 16 + frow) * 144 + (d16 + fcolb) * 2);
#pragma unroll
                for (int ngl = 0; ngl < 2; ++ngl) {
                    int ng = wn * 2 + ngl;
                    uint32_t kh4[4], kl4[4];
                    LDSM4(kh4[0], kh4[1], kh4[2], kh4[3],
                          smb + AKH + (ng * 16 + frow) * 144 + (d16 + fcolb) * 2);
                    LDSM4(kl4[0], kl4[1], kl4[2], kl4[3],
                          smb + AKL + (ng * 16 + frow) * 144 + (d16 + fcolb) * 2);
                    uint32_t f0h[2] = {kh4[0], kh4[2]}, f1h[2] = {kh4[1], kh4[3]};
                    uint32_t f0l[2] = {kl4[0], kl4[2]}, f1l[2] = {kl4[1], kl4[3]};
                    MMA_OP(aqk[2 * ngl],     ah, f0h);
                    MMA_OP(aqk[2 * ngl],     ah, f0l);
                    MMA_OP(aqk[2 * ngl],     al, f0h);
                    MMA_OP(aqk[2 * ngl + 1], ah, f1h);
                    MMA_OP(aqk[2 * ngl + 1], ah, f1l);
                    MMA_OP(aqk[2 * ngl + 1], al, f1h);
                }
                if (first) {
#pragma unroll
                    for (int ngl = 0; ngl < 4; ++ngl) {
                        int lr = (wn * 4 + ngl) * 16;
                        uint32_t e4h[4];
                        uint32_t ra = (uint32_t)((base + lr + frow) & 127) * 144 + (d16 + fcolb) * 2;
                        LDSM4(e4h[0], e4h[1], e4h[2], e4h[3], smb + AEKH + ra);
                        uint32_t f0h[2] = {e4h[0], e4h[2]}, f1h[2] = {e4h[1], e4h[3]};
                        MMA_OP(au[2 * ngl],     ah, f0h);
                        MMA_OP(au[2 * ngl],     al, f0h);
                        MMA_OP(au[2 * ngl + 1], ah, f1h);
                        MMA_OP(au[2 * ngl + 1], al, f1h);
                    }
                } else {
#pragma unroll
                    for (int ngl = 0; ngl < 2; ++ngl) {
                        int lr = 64 + (wn * 2 + ngl) * 16;
                        uint32_t e4h[4];
                        uint32_t ra = (uint32_t)((base + lr + frow) & 127) * 144 + (d16 + fcolb) * 2;
                        LDSM4(e4h[0], e4h[1], e4h[2], e4h[3], smb + AEKH + ra);
                        uint32_t f0h[2] = {e4h[0], e4h[2]}, f1h[2] = {e4h[1], e4h[3]};
                        MMA_OP(au[2 * ngl],     ah, f0h);
                        MMA_OP(au[2 * ngl],     al, f0h);
                        MMA_OP(au[2 * ngl + 1], ah, f1h);
                        MMA_OP(au[2 * ngl + 1], al, f1h);
                    }
                }
            }
#pragma unroll
            for (int ia = 0; ia < 4; ++ia) {
                int kcol = (wn * 2 + (ia >> 1)) * 16 + (ia & 1) * 8 + ccol;
                Sb[crow * 68 + kcol]           = aqk[ia][0];
                Sb[crow * 68 + kcol + 1]       = aqk[ia][1];
                Sb[(crow + 8) * 68 + kcol]     = aqk[ia][2];
                Sb[(crow + 8) * 68 + kcol + 1] = aqk[ia][3];
            }
            int cnt = first ? 8 : 4;
            for (int ia = 0; ia < cnt; ++ia) {
                int lr = (first ? (wn * 4 + (ia >> 1)) * 16
                                : 64 + (wn * 2 + (ia >> 1)) * 16) + (ia & 1) * 8 + ccol;
                int p0 = (base + lr) & 127;
                int p1 = (base + lr + 1) & 127;
                Us[crow * 132 + p0]       = au[ia][0];
                Us[crow * 132 + p1]       = au[ia][1];
                Us[(crow + 8) * 132 + p0] = au[ia][2];
                Us[(crow + 8) * 132 + p1] = au[ia][3];
            }
        }
        __syncthreads();

        // ---- online softmax ----
        float p[16];
        {
            int qg = q0 + srow;
            float mx = -1e30f;
#pragma unroll
            for (int j = 0; j < 16; ++j) {
                int c = spart * 16 + j;
                int pc = (base + c - srow + 63) & 127;
                float s = (Sb[srow * 68 + c] + Us[srow * 132 + pc]) * 0.125f;
                if (k0 + c > qg) s = -1e30f;
                p[j] = s;
                mx = fmaxf(mx, s);
            }
            mx = fmaxf(mx, __shfl_xor_sync(0xffffffffu, mx, 1));
            mx = fmaxf(mx, __shfl_xor_sync(0xffffffffu, mx, 2));
            float mold = mS[srow];
            float mnew = fmaxf(mold, mx);
            float fct = __expf(mold - mnew);
            float rs = 0.f;
#pragma unroll
            for (int j = 0; j < 16; ++j) { p[j] = __expf(p[j] - mnew); rs += p[j]; }
            rs += __shfl_xor_sync(0xffffffffu, rs, 1);
            rs += __shfl_xor_sync(0xffffffffu, rs, 2);
            if (spart == 0) {
                mS[srow] = mnew;
                lS[srow] = lS[srow] * fct + rs;
                fS[srow] = fct;
            }
        }
        __syncthreads();

        // ---- stage P (hi/lo) and sheared Pd (hi only) ----
#pragma unroll
        for (int j2 = 0; j2 < 8; ++j2) {
            int c = spart * 16 + j2 * 2;
            float v0 = p[j2 * 2], v1 = p[j2 * 2 + 1];
            __nv_bfloat16 h0 = __float2bfloat16(v0), h1 = __float2bfloat16(v1);
            __nv_bfloat16 l0 = __float2bfloat16(v0 - __bfloat162float(h0));
            __nv_bfloat16 l1 = __float2bfloat16(v1 - __bfloat162float(h1));
            *(uint32_t*)(sm + APH + srow * 144 + c * 2) = pack2(h0, h1);
            *(uint32_t*)(sm + APL + srow * 144 + c * 2) = pack2(l0, l1);
            int r = c - srow + 63;
            *(uint16_t*)(sm + APDH + srow * 272 + r * 2) = bf16bits(h0);
            *(uint16_t*)(sm + APDH + srow * 272 + (r + 1) * 2) = bf16bits(h1);
        }
        {
            float f0 = fS[crow], f1 = fS[crow + 8];
#pragma unroll
            for (int ni = 0; ni < 4; ++ni) {
                acc[ni][0] *= f0; acc[ni][1] *= f0;
                acc[ni][2] *= f1; acc[ni][3] *= f1;
            }
        }
        __syncthreads();

        // ---- O += P·V (full hi/lo x3) ----
#pragma unroll
        for (int k16 = 0; k16 < 64; k16 += 16) {
            uint32_t ph[4], pl[4];
            LDSM4(ph[0], ph[1], ph[2], ph[3],
                  smb + APH + (wq * 16 + frow) * 144 + (k16 + fcolb) * 2);
            LDSM4(pl[0], pl[1], pl[2], pl[3],
                  smb + APL + (wq * 16 + frow) * 144 + (k16 + fcolb) * 2);
#pragma unroll
            for (int ngl = 0; ngl < 2; ++ngl) {
                int ng = wn * 2 + ngl;
                uint32_t vh4[4], vl4[4];
                LDSM4T(vh4[0], vh4[1], vh4[2], vh4[3],
                       smb + AVH + (k16 + frow) * 144 + (ng * 16 + fcolb) * 2);
                LDSM4T(vl4[0], vl4[1], vl4[2], vl4[3],
                       smb + AVL + (k16 + frow) * 144 + (ng * 16 + fcolb) * 2);
                uint32_t f0h[2] = {vh4[0], vh4[1]}, f1h[2] = {vh4[2], vh4[3]};
                uint32_t f0l[2] = {vl4[0], vl4[1]}, f1l[2] = {vl4[2], vl4[3]};
                MMA_OP(acc[2 * ngl],     ph, f0h);
                MMA_OP(acc[2 * ngl],     ph, f0l);
                MMA_OP(acc[2 * ngl],     pl, f0h);
                MMA_OP(acc[2 * ngl + 1], ph, f1h);
                MMA_OP(acc[2 * ngl + 1], ph, f1l);
                MMA_OP(acc[2 * ngl + 1], pl, f1h);
            }
        }
        // ---- O += Pd·Ev (banded; both hi only) ----
        {
            const int rs0 = 48 - wq * 16;
#pragma unroll
            for (int k5 = 0; k5 < 5; ++k5) {
                int r16 = rs0 + k5 * 16;
                uint32_t ph[4];
                LDSM4(ph[0], ph[1], ph[2], ph[3],
                      smb + APDH + (wq * 16 + frow) * 272 + (r16 + fcolb) * 2);
#pragma unroll
                for (int ngl = 0; ngl < 2; ++ngl) {
                    int ng = wn * 2 + ngl;
                    uint32_t eh4[4];
                    uint32_t ra = (uint32_t)((base + r16 + frow) & 127) * 144 + (ng * 16 + fcolb) * 2;
                    LDSM4T(eh4[0], eh4[1], eh4[2], eh4[3], smb + AEVH + ra);
                    uint32_t f0h[2] = {eh4[0], eh4[1]}, f1h[2] = {eh4[2], eh4[3]};
                    MMA_OP(acc[2 * ngl],     ph, f0h);
                    MMA_OP(acc[2 * ngl + 1], ph, f1h);
                }
            }
        }
    }

    float inv0 = 1.f / lS[crow];
    float inv1 = 1.f / lS[crow + 8];
    __nv_bfloat16* Ogh = Oh + (size_t)(b * LL + q0) * DD + h * HD;
    __nv_bfloat16* Ogl = Ol + (size_t)(b * LL + q0) * DD + h * HD;
#pragma unroll
    for (int ia = 0; ia < 4; ++ia) {
        int col = wn * 32 + (ia >> 1) * 16 + (ia & 1) * 8 + ccol;
#pragma unroll
        for (int hf = 0; hf < 2; ++hf) {
            float v0 = acc[ia][hf * 2]     * (hf ? inv1 : inv0);
            float v1 = acc[ia][hf * 2 + 1] * (hf ? inv1 : inv0);
            __nv_bfloat16 h0 = __float2bfloat16(v0), h1 = __float2bfloat16(v1);
            __nv_bfloat16 l0 = __float2bfloat16(v0 - __bfloat162float(h0));
            __nv_bfloat16 l1 = __float2bfloat16(v1 - __bfloat162float(h1));
            size_t off = (size_t)(crow + hf * 8) * DD + col;
            *(uint32_t*)&Ogh[off] = pack2(h0, h1);
            *(uint32_t*)&Ogl[off] = pack2(l0, l1);
        }
    }
}

// ---------------------------------------------------------------------------
// Launch
// ---------------------------------------------------------------------------
extern "C" void kernel_launch(void* const* d_in, const int* in_sizes, int n_in,
                              void* d_out, int out_size) {
    const float* x   = (const float*)d_in[0];
    const float* Wq  = (const float*)d_in[1];
    const float* Wk  = (const float*)d_in[2];
    const float* Wv  = (const float*)d_in[3];
    const float* Wo  = (const float*)d_in[4];
    const float* pek = (const float*)d_in[5];
    const float* pev = (const float*)d_in[6];
    float* out = (float*)d_out;

    __nv_bfloat16 *xh, *xl, *wh, *wl, *wqh, *wql, *wkh, *wkl, *wvh, *wvl;
    __nv_bfloat16 *Qh, *Ql, *Kh, *Kl, *Vh, *Vl, *Oh, *Ol;
    __nv_bfloat16 *pekh, *pekl, *pevh, *pevl;
    cudaGetSymbolAddress((void**)&xh, g_xh);
    cudaGetSymbolAddress((void**)&xl, g_xl);
    cudaGetSymbolAddress((void**)&wh, g_wh);
    cudaGetSymbolAddress((void**)&wl, g_wl);
    cudaGetSymbolAddress((void**)&wqh, g_wqh);
    cudaGetSymbolAddress((void**)&wql, g_wql);
    cudaGetSymbolAddress((void**)&wkh, g_wkh);
    cudaGetSymbolAddress((void**)&wkl, g_wkl);
    cudaGetSymbolAddress((void**)&wvh, g_wvh);
    cudaGetSymbolAddress((void**)&wvl, g_wvl);
    cudaGetSymbolAddress((void**)&Qh, g_Qh);
    cudaGetSymbolAddress((void**)&Ql, g_Ql);
    cudaGetSymbolAddress((void**)&Kh, g_Kh);
    cudaGetSymbolAddress((void**)&Kl, g_Kl);
    cudaGetSymbolAddress((void**)&Vh, g_Vh);
    cudaGetSymbolAddress((void**)&Vl, g_Vl);
    cudaGetSymbolAddress((void**)&Oh, g_Oh);
    cudaGetSymbolAddress((void**)&Ol, g_Ol);
    cudaGetSymbolAddress((void**)&pekh, g_pekh);
    cudaGetSymbolAddress((void**)&pekl, g_pekl);
    cudaGetSymbolAddress((void**)&pevh, g_pevh);
    cudaGetSymbolAddress((void**)&pevl, g_pevl);

    cudaFuncSetAttribute(gemm_mma, cudaFuncAttributeMaxDynamicSharedMemorySize, GEMM_SMEM);
    cudaFuncSetAttribute(gemm_qkv, cudaFuncAttributeMaxDynamicSharedMemorySize, GEMM_SMEM);
    cudaFuncSetAttribute(attn_fused, cudaFuncAttributeMaxDynamicSharedMemorySize, ATTN_SMEM);

    const int n4w = DD * DD / 4;
    dim3 ggemm(DD / 128, MROWS / 128);
    dim3 gqkv(3 * DD / 128, MROWS / 128);

    split6_kernel<<<7426, 256>>>(x, Wq, Wk, Wv, pek, pev,
                                 xh, xl, wqh, wql, wkh, wkl, wvh, wvl,
                                 pekh, pekl, pevh, pevl);
    gemm_qkv<<<gqkv, 256, GEMM_SMEM>>>(xh, xl, wqh, wql, wkh, wkl, wvh, wvl,
                                       Qh, Ql, Kh, Kl, Vh, Vl);
    split_kernel<<<(n4w + 255) / 256, 256>>>(Wo, wh, wl, n4w);
    attn_fused<<<dim3(16, 64), 256, ATTN_SMEM>>>(Qh, Ql, Kh, Kl, Vh, Vl,
                                                 pekh, pevh, Oh, Ol);
    gemm_mma<<<ggemm, 256, GEMM_SMEM>>>(Oh, Ol, wh, wl, out, nullptr, nullptr);
}

// round 17
// speedup vs baseline: 1.2795x; 1.0405x over previous
#include <cuda_runtime.h>
#include <cuda_bf16.h>
#include <cstdint>

// Problem constants
#define BB 4
#define LL 1024
#define DD 1024
#define HH 16
#define HD 64
#define MROWS 4096           // B*L
#define PEN 2049

// Scratch (device globals; allocation is forbidden)
__device__ __nv_bfloat16 g_xh[MROWS * DD];
__device__ __nv_bfloat16 g_xl[MROWS * DD];
__device__ __nv_bfloat16 g_wqh[DD * DD];
__device__ __nv_bfloat16 g_wql[DD * DD];
__device__ __nv_bfloat16 g_wkh[DD * DD];
__device__ __nv_bfloat16 g_wkl[DD * DD];
__device__ __nv_bfloat16 g_wvh[DD * DD];
__device__ __nv_bfloat16 g_wvl[DD * DD];
__device__ __nv_bfloat16 g_wh[DD * DD];
__device__ __nv_bfloat16 g_wl[DD * DD];
__device__ __nv_bfloat16 g_Qh[MROWS * DD];
__device__ __nv_bfloat16 g_Ql[MROWS * DD];
__device__ __nv_bfloat16 g_Kh[MROWS * DD];
__device__ __nv_bfloat16 g_Kl[MROWS * DD];
__device__ __nv_bfloat16 g_Vh[MROWS * DD];
__device__ __nv_bfloat16 g_Vl[MROWS * DD];
__device__ __nv_bfloat16 g_Oh[MROWS * DD];
__device__ __nv_bfloat16 g_Ol[MROWS * DD];
__device__ __nv_bfloat16 g_pekh[PEN * HD];
__device__ __nv_bfloat16 g_pekl[PEN * HD];
__device__ __nv_bfloat16 g_pevh[PEN * HD];
__device__ __nv_bfloat16 g_pevl[PEN * HD];

__device__ __forceinline__ uint32_t smem_u32(const void* p) {
    uint32_t a;
    asm("{ .reg .u64 t; cvta.to.shared.u64 t, %1; cvt.u32.u64 %0, t; }" : "=r"(a) : "l"(p));
    return a;
}

#define MMA_OP(c, af, bf) \
    asm volatile("mma.sync.aligned.m16n8k16.row.col.f32.bf16.bf16.f32 " \
                 "{%0,%1,%2,%3}, {%4,%5,%6,%7}, {%8,%9}, {%0,%1,%2,%3};" \
                 : "+f"((c)[0]), "+f"((c)[1]), "+f"((c)[2]), "+f"((c)[3]) \
                 : "r"((af)[0]), "r"((af)[1]), "r"((af)[2]), "r"((af)[3]), \
                   "r"((bf)[0]), "r"((bf)[1]))

#define LDSM4(d0,d1,d2,d3,a) \
    asm volatile("ldmatrix.sync.aligned.m8n8.x4.shared.b16 {%0,%1,%2,%3}, [%4];" \
                 : "=r"(d0), "=r"(d1), "=r"(d2), "=r"(d3) : "r"(a))
#define LDSM4T(d0,d1,d2,d3,a) \
    asm volatile("ldmatrix.sync.aligned.m8n8.x4.trans.shared.b16 {%0,%1,%2,%3}, [%4];" \
                 : "=r"(d0), "=r"(d1), "=r"(d2), "=r"(d3) : "r"(a))

#define CP16(dst, src) \
    asm volatile("cp.async.cg.shared.global [%0], [%1], 16;" :: "r"(dst), "l"(src))
#define CPWAIT() \
    asm volatile("cp.async.commit_group;\n\tcp.async.wait_group 0;" ::: "memory")

__device__ __forceinline__ uint32_t pack2(__nv_bfloat16 a, __nv_bfloat16 b) {
    __nv_bfloat162 t(a, b);
    return *reinterpret_cast<uint32_t*>(&t);
}
__device__ __forceinline__ uint16_t bf16bits(__nv_bfloat16 h) {
    return *reinterpret_cast<uint16_t*>(&h);
}

// ---------------------------------------------------------------------------
// fp32 -> bf16 hi/lo split
// ---------------------------------------------------------------------------
__device__ __forceinline__ void split4(const float* s, __nv_bfloat16* h,
                                       __nv_bfloat16* l, int i) {
    float4 v = ((const float4*)s)[i];
    __nv_bfloat16 h0 = __float2bfloat16(v.x);
    __nv_bfloat16 h1 = __float2bfloat16(v.y);
    __nv_bfloat16 h2 = __float2bfloat16(v.z);
    __nv_bfloat16 h3 = __float2bfloat16(v.w);
    __nv_bfloat16 l0 = __float2bfloat16(v.x - __bfloat162float(h0));
    __nv_bfloat16 l1 = __float2bfloat16(v.y - __bfloat162float(h1));
    __nv_bfloat16 l2 = __float2bfloat16(v.z - __bfloat162float(h2));
    __nv_bfloat16 l3 = __float2bfloat16(v.w - __bfloat162float(h3));
    ((uint2*)h)[i] = make_uint2(pack2(h0, h1), pack2(h2, h3));
    ((uint2*)l)[i] = make_uint2(pack2(l0, l1), pack2(l2, l3));
}

__global__ __launch_bounds__(256)
void split_kernel(const float* __restrict__ s, __nv_bfloat16* __restrict__ h,
                  __nv_bfloat16* __restrict__ l, int n4) {
    int i = blockIdx.x * 256 + threadIdx.x;
    if (i >= n4) return;
    split4(s, h, l, i);
}

__global__ __launch_bounds__(256)
void split6_kernel(const float* __restrict__ x, const float* __restrict__ Wq,
                   const float* __restrict__ Wk, const float* __restrict__ Wv,
                   const float* __restrict__ pek, const float* __restrict__ pev,
                   __nv_bfloat16* __restrict__ xh, __nv_bfloat16* __restrict__ xl,
                   __nv_bfloat16* __restrict__ wqh, __nv_bfloat16* __restrict__ wql,
                   __nv_bfloat16* __restrict__ wkh, __nv_bfloat16* __restrict__ wkl,
                   __nv_bfloat16* __restrict__ wvh, __nv_bfloat16* __restrict__ wvl,
                   __nv_bfloat16* __restrict__ pkh, __nv_bfloat16* __restrict__ pkl,
                   __nv_bfloat16* __restrict__ pvh, __nv_bfloat16* __restrict__ pvl) {
    int blk = blockIdx.x;
    const float* s; __nv_bfloat16 *h, *l; int i, n4;
    if (blk < 4096)      { s = x;   h = xh;  l = xl;  i = blk * 256 + threadIdx.x; n4 = 1048576; }
    else if (blk < 5120) { s = Wq;  h = wqh; l = wql; i = (blk - 4096) * 256 + threadIdx.x; n4 = 262144; }
    else if (blk < 6144) { s = Wk;  h = wkh; l = wkl; i = (blk - 5120) * 256 + threadIdx.x; n4 = 262144; }
    else if (blk < 7168) { s = Wv;  h = wvh; l = wvl; i = (blk - 6144) * 256 + threadIdx.x; n4 = 262144; }
    else if (blk < 7297) { s = pek; h = pkh; l = pkl; i = (blk - 7168) * 256 + threadIdx.x; n4 = 32784; }
    else                 { s = pev; h = pvh; l = pvl; i = (blk - 7297) * 256 + threadIdx.x; n4 = 32784; }
    if (i >= n4) return;
    split4(s, h, l, i);
}

// ---------------------------------------------------------------------------
// GEMM core: 256 threads, warp grid 2(m) x 4(n), tile 64x32, 2 CTAs/SM.
// ---------------------------------------------------------------------------
#define GKDIM 1024
#define NIT 32
#define TILE_B 10240
#define STAGE_B (4 * TILE_B)
#define GEMM_SMEM (2 * STAGE_B)

__device__ __forceinline__
void gemm_body(char* sm, uint32_t smb,
               const __nv_bfloat16* Ah, const __nv_bfloat16* Al,
               const __nv_bfloat16* Bh, const __nv_bfloat16* Bl,
               int m0, int n0,
               float* C, __nv_bfloat16* Ch, __nv_bfloat16* Cl) {
    const int tid = threadIdx.x;
    const int wid = tid >> 5, lane = tid & 31;
    const int wm = wid & 1, wn = wid >> 1;

    const __nv_bfloat16* srcs[4] = {
        Ah + (size_t)m0 * GKDIM, Al + (size_t)m0 * GKDIM,
        Bh + (size_t)n0 * GKDIM, Bl + (size_t)n0 * GKDIM };

    auto stage_load = [&](int kc, int s) {
#pragma unroll
        for (int rep = 0; rep < 8; ++rep) {
            int idx = tid + rep * 256;
            int tile = idx >> 9;
            int r = (idx >> 2) & 127;
            int c = idx & 3;
            const void* gp = srcs[tile] + (size_t)r * GKDIM + kc * 32 + c * 8;
            uint32_t dp = smb + s * STAGE_B + tile * TILE_B + r * 80 + c * 16;
            CP16(dp, gp);
        }
        asm volatile("cp.async.commit_group;");
    };

    float acc[4][4][4];
#pragma unroll
    for (int i = 0; i < 4; ++i)
#pragma unroll
        for (int j = 0; j < 4; ++j)
#pragma unroll
            for (int k = 0; k < 4; ++k) acc[i][j][k] = 0.f;

    stage_load(0, 0);

    for (int it = 0; it < NIT; ++it) {
        if (it + 1 < NIT) {
            stage_load(it + 1, (it + 1) & 1);
            asm volatile("cp.async.wait_group 1;");
        } else {
            asm volatile("cp.async.wait_group 0;");
        }
        __syncthreads();

        const uint32_t base = smb + (it & 1) * STAGE_B;
        const uint32_t aHb = base, aLb = base + TILE_B;
        const uint32_t bHb = base + 2 * TILE_B, bLb = base + 3 * TILE_B;
        const int arow = wm * 64 + (lane & 15);
        const int acolb = (lane & 16) >> 1;
        const int brow = wn * 32 + (lane & 7);
        const int bcolb = lane & 8;

#pragma unroll
        for (int k16 = 0; k16 < 32; k16 += 16) {
            uint32_t ah[4][4], al[4][4], bh[4][2], bl[4][2];
#pragma unroll
            for (int mi = 0; mi < 4; ++mi) {
                uint32_t ad = aHb + ((arow + mi * 16) * 40 + k16 + acolb) * 2;
                LDSM4(ah[mi][0], ah[mi][1], ah[mi][2], ah[mi][3], ad);
                uint32_t ad2 = aLb + ((arow + mi * 16) * 40 + k16 + acolb) * 2;
                LDSM4(al[mi][0], al[mi][1], al[mi][2], al[mi][3], ad2);
            }
#pragma unroll
            for (int ni = 0; ni < 4; ++ni) {
                uint32_t bd = bHb + ((brow + ni * 8) * 40 + k16 + bcolb) * 2;
                asm volatile("ldmatrix.sync.aligned.m8n8.x2.shared.b16 {%0,%1}, [%2];"
                             : "=r"(bh[ni][0]), "=r"(bh[ni][1]) : "r"(bd));
                uint32_t bd2 = bLb + ((brow + ni * 8) * 40 + k16 + bcolb) * 2;
                asm volatile("ldmatrix.sync.aligned.m8n8.x2.shared.b16 {%0,%1}, [%2];"
                             : "=r"(bl[ni][0]), "=r"(bl[ni][1]) : "r"(bd2));
            }
#pragma unroll
            for (int mi = 0; mi < 4; ++mi)
#pragma unroll
                for (int ni = 0; ni < 4; ++ni)
                    MMA_OP(acc[mi][ni], ah[mi], bh[ni]);
#pragma unroll
            for (int mi = 0; mi < 4; ++mi)
#pragma unroll
                for (int ni = 0; ni < 4; ++ni)
                    MMA_OP(acc[mi][ni], ah[mi], bl[ni]);
#pragma unroll
            for (int mi = 0; mi < 4; ++mi)
#pragma unroll
                for (int ni = 0; ni < 4; ++ni)
                    MMA_OP(acc[mi][ni], al[mi], bh[ni]);
        }
        __syncthreads();
    }

    const int crow = m0 + wm * 64 + (lane >> 2);
    const int ccol = n0 + wn * 32 + (lane & 3) * 2;
    if (Ch) {
#pragma unroll
        for (int mi = 0; mi < 4; ++mi)
#pragma unroll
            for (int ni = 0; ni < 4; ++ni) {
                size_t r0 = (size_t)(crow + mi * 16) * DD + ccol + ni * 8;
                size_t r1 = (size_t)(crow + mi * 16 + 8) * DD + ccol + ni * 8;
#pragma unroll
                for (int half = 0; half < 2; ++half) {
                    float v0 = acc[mi][ni][half * 2], v1 = acc[mi][ni][half * 2 + 1];
                    __nv_bfloat16 h0 = __float2bfloat16(v0), h1 = __float2bfloat16(v1);
                    __nv_bfloat16 q0b = __float2bfloat16(v0 - __bfloat162float(h0));
                    __nv_bfloat16 q1b = __float2bfloat16(v1 - __bfloat162float(h1));
                    size_t r = half ? r1 : r0;
                    *(uint32_t*)&Ch[r] = pack2(h0, h1);
                    *(uint32_t*)&Cl[r] = pack2(q0b, q1b);
                }
            }
    } else {
#pragma unroll
        for (int mi = 0; mi < 4; ++mi)
#pragma unroll
            for (int ni = 0; ni < 4; ++ni) {
                size_t r0 = (size_t)(crow + mi * 16) * DD + ccol + ni * 8;
                size_t r1 = (size_t)(crow + mi * 16 + 8) * DD + ccol + ni * 8;
                *(float2*)&C[r0] = make_float2(acc[mi][ni][0], acc[mi][ni][1]);
                *(float2*)&C[r1] = make_float2(acc[mi][ni][2], acc[mi][ni][3]);
            }
    }
}

__global__ __launch_bounds__(256, 2)
void gemm_mma(const __nv_bfloat16* __restrict__ Ah, const __nv_bfloat16* __restrict__ Al,
              const __nv_bfloat16* __restrict__ Bh, const __nv_bfloat16* __restrict__ Bl,
              float* __restrict__ C,
              __nv_bfloat16* __restrict__ Ch, __nv_bfloat16* __restrict__ Cl) {
    extern __shared__ __align__(128) char sm[];
    gemm_body(sm, smem_u32(sm), Ah, Al, Bh, Bl,
              blockIdx.y * 128, blockIdx.x * 128, C, Ch, Cl);
}

__global__ __launch_bounds__(256, 2)
void gemm_qkv(const __nv_bfloat16* __restrict__ Ah, const __nv_bfloat16* __restrict__ Al,
              const __nv_bfloat16* __restrict__ Bh0, const __nv_bfloat16* __restrict__ Bl0,
              const __nv_bfloat16* __restrict__ Bh1, const __nv_bfloat16* __restrict__ Bl1,
              const __nv_bfloat16* __restrict__ Bh2, const __nv_bfloat16* __restrict__ Bl2,
              __nv_bfloat16* __restrict__ Ch0, __nv_bfloat16* __restrict__ Cl0,
              __nv_bfloat16* __restrict__ Ch1, __nv_bfloat16* __restrict__ Cl1,
              __nv_bfloat16* __restrict__ Ch2, __nv_bfloat16* __restrict__ Cl2) {
    extern __shared__ __align__(128) char sm[];
    int sel = blockIdx.x >> 3;
    int n0 = (blockIdx.x & 7) * 128;
    const __nv_bfloat16* Bh = (sel == 0) ? Bh0 : (sel == 1) ? Bh1 : Bh2;
    const __nv_bfloat16* Bl = (sel == 0) ? Bl0 : (sel == 1) ? Bl1 : Bl2;
    __nv_bfloat16* Ch = (sel == 0) ? Ch0 : (sel == 1) ? Ch1 : Ch2;
    __nv_bfloat16* Cl = (sel == 0) ? Cl0 : (sel == 1) ? Cl1 : Cl2;
    gemm_body(sm, smem_u32(sm), Ah, Al, Bh, Bl,
              blockIdx.y * 128, n0, nullptr, Ch, Cl);
}

// ---------------------------------------------------------------------------
// Fused flash attention. R16: register-resident softmax (no Sb buffer; row
// stats combined via 64x2 pmax/psum arrays + shfl), U = Qh·Ekh only.
// ---------------------------------------------------------------------------
#define AQH   0
#define AQL   9216
#define AKH   18432
#define AKL   27648
#define AVH   36864
#define AVL   46080
#define AEKH  55296                  // 128 x 144B (hi only)
#define AEVH  73728                  // 128 x 144B (hi only)
#define AU    92160                  // 64 x 132 fp32
#define APH   125952
#define APL   135168
#define APDH  144384                 // sheared P hi, 64 x 272B
#define ASTAT 161792                 // mS 64 | lS 64 | pmax 128 | psum 128 (fp32)
#define ATTN_SMEM (161792 + 1536)

__global__ __launch_bounds__(256)
void attn_fused(const __nv_bfloat16* __restrict__ Qh, const __nv_bfloat16* __restrict__ Ql,
                const __nv_bfloat16* __restrict__ Kh, const __nv_bfloat16* __restrict__ Kl,
                const __nv_bfloat16* __restrict__ Vh, const __nv_bfloat16* __restrict__ Vl,
                const __nv_bfloat16* __restrict__ Ekh,
                const __nv_bfloat16* __restrict__ Evh,
                __nv_bfloat16* __restrict__ Oh, __nv_bfloat16* __restrict__ Ol) {
    extern __shared__ __align__(128) char sm[];
    const uint32_t smb = smem_u32(sm);
    const int qt = 15 - blockIdx.x;
    const int q0 = qt * 64;
    const int bh = blockIdx.y;
    const int b = bh >> 4, h = bh & 15;
    const int tid = threadIdx.x;
    const int wid = tid >> 5, lane = tid & 31;
    const int wq = wid & 3, wn = wid >> 2;
    const int frow = lane & 15;
    const int fcolb = (lane >> 4) << 3;
    const int crow = wq * 16 + (lane >> 2);
    const int ccol = (lane & 3) * 2;

    float* mS = (float*)(sm + ASTAT);
    float* lS = mS + 64;
    float* pmax = mS + 128;     // [row*2 + wn]
    float* psum = mS + 256;     // [row*2 + wn]
    float* Us = (float*)(sm + AU);

    if (tid < 64) { mS[tid] = -1e30f; lS[tid] = 0.f; }
    // zero Pd once (complement slots stay zero across all iterations)
    {
        uint4 z = make_uint4(0, 0, 0, 0);
        for (int i = tid; i < 64 * 17; i += 256) {
            int r = i / 17, c = i % 17;
            *(uint4*)(sm + APDH + r * 272 + c * 16) = z;
        }
    }

    // stage Q (once)
    {
        const __nv_bfloat16* gq = Qh + (size_t)(b * LL + q0) * DD + h * HD;
        const __nv_bfloat16* gql = Ql + (size_t)(b * LL + q0) * DD + h * HD;
#pragma unroll
        for (int t = 0; t < 4; ++t) {
            int i = tid + t * 256;
            int tt = i >> 9;
            int r = (i >> 3) & 63;
            int c = i & 7;
            const __nv_bfloat16* sp = (tt ? gql : gq) + (size_t)r * DD + c * 8;
            CP16(smb + (tt ? AQL : AQH) + r * 144 + c * 16, sp);
        }
    }

    float acc[4][4];
#pragma unroll
    for (int i = 0; i < 4; ++i)
#pragma unroll
        for (int j = 0; j < 4; ++j) acc[i][j] = 0.f;

    for (int k0 = 0; k0 <= q0; k0 += 64) {
        const int base = k0 - q0 + 961;
        const bool first = (k0 == 0);
        __syncthreads();
        // stage K, V (hi/lo)
        {
            const __nv_bfloat16* g0 = Kh + (size_t)(b * LL + k0) * DD + h * HD;
            const __nv_bfloat16* g1 = Kl + (size_t)(b * LL + k0) * DD + h * HD;
            const __nv_bfloat16* g2 = Vh + (size_t)(b * LL + k0) * DD + h * HD;
            const __nv_bfloat16* g3 = Vl + (size_t)(b * LL + k0) * DD + h * HD;
#pragma unroll
            for (int t = 0; t < 8; ++t) {
                int i = tid + t * 256;
                int tile = i >> 9;
                int r = (i >> 3) & 63;
                int c = i & 7;
                const __nv_bfloat16* sp =
                    ((tile == 0) ? g0 : (tile == 1) ? g1 : (tile == 2) ? g2 : g3)
                    + (size_t)r * DD + c * 8;
                uint32_t off = (tile == 0) ? AKH : (tile == 1) ? AKL : (tile == 2) ? AVH : AVL;
                CP16(smb + off + r * 144 + c * 16, sp);
            }
        }
        // stage Ek/Ev (HI only, circular): first iter 128 rows, else 64 new
        {
            int g0r = base + (first ? 0 : 64);
            int nt = first ? 8 : 4;
            int rsh = first ? 10 : 9;
            int rmask = first ? 127 : 63;
            for (int t = 0; t < nt; ++t) {
                int i = tid + t * 256;
                int tile = i >> rsh;
                int rr = (i >> 3) & rmask;
                int c = i & 7;
                int g = g0r + rr;
                const __nv_bfloat16* sp = (tile ? Evh : Ekh) + (size_t)g * HD + c * 8;
                uint32_t off = tile ? AEVH : AEKH;
                CP16(smb + off + (uint32_t)(g & 127) * 144 + c * 16, sp);
            }
        }
        CPWAIT();
        __syncthreads();

        // ---- S = Q·K^T (hi/lo x3) and new U columns = Qh·Ekh ----
        float aqk[4][4];
        {
            float au[8][4];
#pragma unroll
            for (int i = 0; i < 4; ++i)
#pragma unroll
                for (int j = 0; j < 4; ++j) aqk[i][j] = 0.f;
#pragma unroll
            for (int i = 0; i < 8; ++i)
#pragma unroll
                for (int j = 0; j < 4; ++j) au[i][j] = 0.f;

#pragma unroll
            for (int d16 = 0; d16 < 64; d16 += 16) {
                uint32_t ah[4], al[4];
                LDSM4(ah[0], ah[1], ah[2], ah[3],
                      smb + AQH + (wq * 16 + frow) * 144 + (d16 + fcolb) * 2);
                LDSM4(al[0], al[1], al[2], al[3],
                      smb + AQL + (wq * 16 + frow) * 144 + (d16 + fcolb) * 2);
#pragma unroll
                for (int ngl = 0; ngl < 2; ++ngl) {
                    int ng = wn * 2 + ngl;
                    uint32_t kh4[4], kl4[4];
                    LDSM4(kh4[0], kh4[1], kh4[2], kh4[3],
                          smb + AKH + (ng * 16 + frow) * 144 + (d16 + fcolb) * 2);
                    LDSM4(kl4[0], kl4[1], kl4[2], kl4[3],
                          smb + AKL + (ng * 16 + frow) * 144 + (d16 + fcolb) * 2);
                    uint32_t f0h[2] = {kh4[0], kh4[2]}, f1h[2] = {kh4[1], kh4[3]};
                    uint32_t f0l[2] = {kl4[0], kl4[2]}, f1l[2] = {kl4[1], kl4[3]};
                    MMA_OP(aqk[2 * ngl],     ah, f0h);
                    MMA_OP(aqk[2 * ngl],     ah, f0l);
                    MMA_OP(aqk[2 * ngl],     al, f0h);
                    MMA_OP(aqk[2 * ngl + 1], ah, f1h);
                    MMA_OP(aqk[2 * ngl + 1], ah, f1l);
                    MMA_OP(aqk[2 * ngl + 1], al, f1h);
                }
                if (first) {
#pragma unroll
                    for (int ngl = 0; ngl < 4; ++ngl) {
                        int lr = (wn * 4 + ngl) * 16;
                        uint32_t e4h[4];
                        uint32_t ra = (uint32_t)((base + lr + frow) & 127) * 144 + (d16 + fcolb) * 2;
                        LDSM4(e4h[0], e4h[1], e4h[2], e4h[3], smb + AEKH + ra);
                        uint32_t f0h[2] = {e4h[0], e4h[2]}, f1h[2] = {e4h[1], e4h[3]};
                        MMA_OP(au[2 * ngl],     ah, f0h);
                        MMA_OP(au[2 * ngl + 1], ah, f1h);
                    }
                } else {
#pragma unroll
                    for (int ngl = 0; ngl < 2; ++ngl) {
                        int lr = 64 + (wn * 2 + ngl) * 16;
                        uint32_t e4h[4];
                        uint32_t ra = (uint32_t)((base + lr + frow) & 127) * 144 + (d16 + fcolb) * 2;
                        LDSM4(e4h[0], e4h[1], e4h[2], e4h[3], smb + AEKH + ra);
                        uint32_t f0h[2] = {e4h[0], e4h[2]}, f1h[2] = {e4h[1], e4h[3]};
                        MMA_OP(au[2 * ngl],     ah, f0h);
                        MMA_OP(au[2 * ngl + 1], ah, f1h);
                    }
                }
            }
            int cnt = first ? 8 : 4;
            for (int ia = 0; ia < cnt; ++ia) {
                int lr = (first ? (wn * 4 + (ia >> 1)) * 16
                                : 64 + (wn * 2 + (ia >> 1)) * 16) + (ia & 1) * 8 + ccol;
                int p0 = (base + lr) & 127;
                int p1 = (base + lr + 1) & 127;
                Us[crow * 132 + p0]       = au[ia][0];
                Us[crow * 132 + p1]       = au[ia][1];
                Us[(crow + 8) * 132 + p0] = au[ia][2];
                Us[(crow + 8) * 132 + p1] = au[ia][3];
            }
        }
        __syncthreads();   // Us complete (both wn warps)

        // ---- register softmax ----
        float mnew0, mnew1, fct0, fct1;
        {
            float lmax0 = -1e30f, lmax1 = -1e30f;
#pragma unroll
            for (int ia = 0; ia < 4; ++ia) {
                int kc0 = (wn * 2 + (ia >> 1)) * 16 + (ia & 1) * 8 + ccol;
#pragma unroll
                for (int hf = 0; hf < 2; ++hf) {
                    int row = crow + hf * 8;
#pragma unroll
                    for (int c = 0; c < 2; ++c) {
                        int kcol = kc0 + c;
                        int pc = (base + kcol - row + 63) & 127;
                        float s = (aqk[ia][hf * 2 + c] + Us[row * 132 + pc]) * 0.125f;
                        if (k0 + kcol > q0 + row) s = -1e30f;
                        aqk[ia][hf * 2 + c] = s;
                        if (hf == 0) lmax0 = fmaxf(lmax0, s);
                        else         lmax1 = fmaxf(lmax1, s);
                    }
                }
            }
            lmax0 = fmaxf(lmax0, __shfl_xor_sync(0xffffffffu, lmax0, 1));
            lmax0 = fmaxf(lmax0, __shfl_xor_sync(0xffffffffu, lmax0, 2));
            lmax1 = fmaxf(lmax1, __shfl_xor_sync(0xffffffffu, lmax1, 1));
            lmax1 = fmaxf(lmax1, __shfl_xor_sync(0xffffffffu, lmax1, 2));
            if ((lane & 3) == 0) {
                pmax[crow * 2 + wn] = lmax0;
                pmax[(crow + 8) * 2 + wn] = lmax1;
            }
        }
        __syncthreads();
        {
            float g0 = fmaxf(pmax[crow * 2], pmax[crow * 2 + 1]);
            float g1 = fmaxf(pmax[(crow + 8) * 2], pmax[(crow + 8) * 2 + 1]);
            float mold0 = mS[crow], mold1 = mS[crow + 8];
            mnew0 = fmaxf(mold0, g0); mnew1 = fmaxf(mold1, g1);
            fct0 = __expf(mold0 - mnew0); fct1 = __expf(mold1 - mnew1);
            float rs0 = 0.f, rs1 = 0.f;
#pragma unroll
            for (int ia = 0; ia < 4; ++ia) {
#pragma unroll
                for (int c = 0; c < 2; ++c) {
                    float e0 = __expf(aqk[ia][c] - mnew0);
                    float e1 = __expf(aqk[ia][2 + c] - mnew1);
                    aqk[ia][c] = e0; aqk[ia][2 + c] = e1;
                    rs0 += e0; rs1 += e1;
                }
            }
            rs0 += __shfl_xor_sync(0xffffffffu, rs0, 1);
            rs0 += __shfl_xor_sync(0xffffffffu, rs0, 2);
            rs1 += __shfl_xor_sync(0xffffffffu, rs1, 1);
            rs1 += __shfl_xor_sync(0xffffffffu, rs1, 2);
            if ((lane & 3) == 0) {
                psum[crow * 2 + wn] = rs0;
                psum[(crow + 8) * 2 + wn] = rs1;
            }
            // stage P (hi/lo) and sheared Pd (hi only) from registers
#pragma unroll
            for (int ia = 0; ia < 4; ++ia) {
                int kc0 = (wn * 2 + (ia >> 1)) * 16 + (ia & 1) * 8 + ccol;
#pragma unroll
                for (int hf = 0; hf < 2; ++hf) {
                    int row = crow + hf * 8;
                    float v0 = aqk[ia][hf * 2], v1 = aqk[ia][hf * 2 + 1];
                    __nv_bfloat16 h0 = __float2bfloat16(v0), h1 = __float2bfloat16(v1);
                    __nv_bfloat16 l0 = __float2bfloat16(v0 - __bfloat162float(h0));
                    __nv_bfloat16 l1 = __float2bfloat16(v1 - __bfloat162float(h1));
                    *(uint32_t*)(sm + APH + row * 144 + kc0 * 2) = pack2(h0, h1);
                    *(uint32_t*)(sm + APL + row * 144 + kc0 * 2) = pack2(l0, l1);
                    int r = kc0 - row + 63;
                    *(uint16_t*)(sm + APDH + row * 272 + r * 2) = bf16bits(h0);
                    *(uint16_t*)(sm + APDH + row * 272 + (r + 1) * 2) = bf16bits(h1);
                }
            }
            // rescale accumulator with locally-computed factors
#pragma unroll
            for (int ni = 0; ni < 4; ++ni) {
                acc[ni][0] *= fct0; acc[ni][1] *= fct0;
                acc[ni][2] *= fct1; acc[ni][3] *= fct1;
            }
        }
        __syncthreads();   // P/Pd/psum complete
        // designated threads update row stats
        if (wn == 0 && (lane & 3) == 0) {
            mS[crow] = mnew0; mS[crow + 8] = mnew1;
            lS[crow] = lS[crow] * fct0 + psum[crow * 2] + psum[crow * 2 + 1];
            lS[crow + 8] = lS[crow + 8] * fct1 + psum[(crow + 8) * 2] + psum[(crow + 8) * 2 + 1];
        }

        // ---- O += P·V (full hi/lo x3) ----
#pragma unroll
        for (int k16 = 0; k16 < 64; k16 += 16) {
            uint32_t ph[4], pl[4];
            LDSM4(ph[0], ph[1], ph[2], ph[3],
                  smb + APH + (wq * 16 + frow) * 144 + (k16 + fcolb) * 2);
            LDSM4(pl[0], pl[1], pl[2], pl[3],
                  smb + APL + (wq * 16 + frow) * 144 + (k16 + fcolb) * 2);
#pragma unroll
            for (int ngl = 0; ngl < 2; ++ngl) {
                int ng = wn * 2 + ngl;
                uint32_t vh4[4], vl4[4];
                LDSM4T(vh4[0], vh4[1], vh4[2], vh4[3],
                       smb + AVH + (k16 + frow) * 144 + (ng * 16 + fcolb) * 2);
                LDSM4T(vl4[0], vl4[1], vl4[2], vl4[3],
                       smb + AVL + (k16 + frow) * 144 + (ng * 16 + fcolb) * 2);
                uint32_t f0h[2] = {vh4[0], vh4[1]}, f1h[2] = {vh4[2], vh4[3]};
                uint32_t f0l[2] = {vl4[0], vl4[1]}, f1l[2] = {vl4[2], vl4[3]};
                MMA_OP(acc[2 * ngl],     ph, f0h);
                MMA_OP(acc[2 * ngl],     ph, f0l);
                MMA_OP(acc[2 * ngl],     pl, f0h);
                MMA_OP(acc[2 * ngl + 1], ph, f1h);
                MMA_OP(acc[2 * ngl + 1], ph, f1l);
                MMA_OP(acc[2 * ngl + 1], pl, f1h);
            }
        }
        // ---- O += Pd·Ev (banded; both hi only) ----
        {
            const int rs0b = 48 - wq * 16;
#pragma unroll
            for (int k5 = 0; k5 < 5; ++k5) {
                int r16 = rs0b + k5 * 16;
                uint32_t ph[4];
                LDSM4(ph[0], ph[1], ph[2], ph[3],
                      smb + APDH + (wq * 16 + frow) * 272 + (r16 + fcolb) * 2);
#pragma unroll
                for (int ngl = 0; ngl < 2; ++ngl) {
                    int ng = wn * 2 + ngl;
                    uint32_t eh4[4];
                    uint32_t ra = (uint32_t)((base + r16 + frow) & 127) * 144 + (ng * 16 + fcolb) * 2;
                    LDSM4T(eh4[0], eh4[1], eh4[2], eh4[3], smb + AEVH + ra);
                    uint32_t f0h[2] = {eh4[0], eh4[1]}, f1h[2] = {eh4[2], eh4[3]};
                    MMA_OP(acc[2 * ngl],     ph, f0h);
                    MMA_OP(acc[2 * ngl + 1], ph, f1h);
                }
            }
        }
    }

    __syncthreads();   // final lS writes visible
    float inv0 = 1.f / lS[crow];
    float inv1 = 1.f / lS[crow + 8];
    __nv_bfloat16* Ogh = Oh + (size_t)(b * LL + q0) * DD + h * HD;
    __nv_bfloat16* Ogl = Ol + (size_t)(b * LL + q0) * DD + h * HD;
#pragma unroll
    for (int ia = 0; ia < 4; ++ia) {
        int col = wn * 32 + (ia >> 1) * 16 + (ia & 1) * 8 + ccol;
#pragma unroll
        for (int hf = 0; hf < 2; ++hf) {
            float v0 = acc[ia][hf * 2]     * (hf ? inv1 : inv0);
            float v1 = acc[ia][hf * 2 + 1] * (hf ? inv1 : inv0);
            __nv_bfloat16 h0 = __float2bfloat16(v0), h1 = __float2bfloat16(v1);
            __nv_bfloat16 l0 = __float2bfloat16(v0 - __bfloat162float(h0));
            __nv_bfloat16 l1 = __float2bfloat16(v1 - __bfloat162float(h1));
            size_t off = (size_t)(crow + hf * 8) * DD + col;
            *(uint32_t*)&Ogh[off] = pack2(h0, h1);
            *(uint32_t*)&Ogl[off] = pack2(l0, l1);
        }
    }
}

// ---------------------------------------------------------------------------
// Launch
// ---------------------------------------------------------------------------
extern "C" void kernel_launch(void* const* d_in, const int* in_sizes, int n_in,
                              void* d_out, int out_size) {
    const float* x   = (const float*)d_in[0];
    const float* Wq  = (const float*)d_in[1];
    const float* Wk  = (const float*)d_in[2];
    const float* Wv  = (const float*)d_in[3];
    const float* Wo  = (const float*)d_in[4];
    const float* pek = (const float*)d_in[5];
    const float* pev = (const float*)d_in[6];
    float* out = (float*)d_out;

    __nv_bfloat16 *xh, *xl, *wh, *wl, *wqh, *wql, *wkh, *wkl, *wvh, *wvl;
    __nv_bfloat16 *Qh, *Ql, *Kh, *Kl, *Vh, *Vl, *Oh, *Ol;
    __nv_bfloat16 *pekh, *pekl, *pevh, *pevl;
    cudaGetSymbolAddress((void**)&xh, g_xh);
    cudaGetSymbolAddress((void**)&xl, g_xl);
    cudaGetSymbolAddress((void**)&wh, g_wh);
    cudaGetSymbolAddress((void**)&wl, g_wl);
    cudaGetSymbolAddress((void**)&wqh, g_wqh);
    cudaGetSymbolAddress((void**)&wql, g_wql);
    cudaGetSymbolAddress((void**)&wkh, g_wkh);
    cudaGetSymbolAddress((void**)&wkl, g_wkl);
    cudaGetSymbolAddress((void**)&wvh, g_wvh);
    cudaGetSymbolAddress((void**)&wvl, g_wvl);
    cudaGetSymbolAddress((void**)&Qh, g_Qh);
    cudaGetSymbolAddress((void**)&Ql, g_Ql);
    cudaGetSymbolAddress((void**)&Kh, g_Kh);
    cudaGetSymbolAddress((void**)&Kl, g_Kl);
    cudaGetSymbolAddress((void**)&Vh, g_Vh);
    cudaGetSymbolAddress((void**)&Vl, g_Vl);
    cudaGetSymbolAddress((void**)&Oh, g_Oh);
    cudaGetSymbolAddress((void**)&Ol, g_Ol);
    cudaGetSymbolAddress((void**)&pekh, g_pekh);
    cudaGetSymbolAddress((void**)&pekl, g_pekl);
    cudaGetSymbolAddress((void**)&pevh, g_pevh);
    cudaGetSymbolAddress((void**)&pevl, g_pevl);

    cudaFuncSetAttribute(gemm_mma, cudaFuncAttributeMaxDynamicSharedMemorySize, GEMM_SMEM);
    cudaFuncSetAttribute(gemm_qkv, cudaFuncAttributeMaxDynamicSharedMemorySize, GEMM_SMEM);
    cudaFuncSetAttribute(attn_fused, cudaFuncAttributeMaxDynamicSharedMemorySize, ATTN_SMEM);

    const int n4w = DD * DD / 4;
    dim3 ggemm(DD / 128, MROWS / 128);
    dim3 gqkv(3 * DD / 128, MROWS / 128);

    split6_kernel<<<7426, 256>>>(x, Wq, Wk, Wv, pek, pev,
                                 xh, xl, wqh, wql, wkh, wkl, wvh, wvl,
                                 pekh, pekl, pevh, pevl);
    gemm_qkv<<<gqkv, 256, GEMM_SMEM>>>(xh, xl, wqh, wql, wkh, wkl, wvh, wvl,
                                       Qh, Ql, Kh, Kl, Vh, Vl);
    split_kernel<<<(n4w + 255) / 256, 256>>>(Wo, wh, wl, n4w);
    attn_fused<<<dim3(16, 64), 256, ATTN_SMEM>>>(Qh, Ql, Kh, Kl, Vh, Vl,
                                                 pekh, pevh, Oh, Ol);
    gemm_mma<<<ggemm, 256, GEMM_SMEM>>>(Oh, Ol, wh, wl, out, nullptr, nullptr);
}